// round 2
// baseline (speedup 1.0000x reference)
#include <cuda_runtime.h>
#include <math.h>

#define B_    2
#define S_    2048
#define D_    2048
#define H_    16
#define HKV_  4
#define DH_   128
#define NREP_ (H_/HKV_)
#define BS_   (B_*S_)

// Scratch (static device allocations; no cudaMalloc allowed)
__device__ float g_q[BS_*H_*DH_];    // [B,S,H,DH]
__device__ float g_k[BS_*HKV_*DH_];  // [B,S,HKV,DH]
__device__ float g_v[BS_*HKV_*DH_];
__device__ float g_o[BS_*H_*DH_];    // attention out, [B,S,H*DH]

// ---------------- SGEMM: C[M,N] = A[M,K] @ B[K,N], all row-major ----------
// 128x128 tile, BK=8, 256 threads, 8x8 microtile. M,N,K multiples of 128/8.
__global__ __launch_bounds__(256) void sgemm_k(const float* __restrict__ A,
                                               const float* __restrict__ Bm,
                                               float* __restrict__ C,
                                               int M, int N, int K)
{
    __shared__ float As[8][128];
    __shared__ float Bs[8][128];
    const int bx = blockIdx.x, by = blockIdx.y;
    const int tid = threadIdx.x;
    const int tr = tid >> 4, tc = tid & 15;

    const float* Ab = A + (size_t)by * 128 * K;
    const float* Bb = Bm + (size_t)bx * 128;

    float acc[8][8];
    #pragma unroll
    for (int i = 0; i < 8; i++)
        #pragma unroll
        for (int j = 0; j < 8; j++) acc[i][j] = 0.f;

    const int a_r = tid >> 1, a_c = (tid & 1) * 4;
    const int b_r = tid >> 5, b_c = (tid & 31) * 4;

    for (int k0 = 0; k0 < K; k0 += 8) {
        float4 av = *(const float4*)(Ab + (size_t)a_r * K + k0 + a_c);
        As[a_c + 0][a_r] = av.x;
        As[a_c + 1][a_r] = av.y;
        As[a_c + 2][a_r] = av.z;
        As[a_c + 3][a_r] = av.w;
        *(float4*)(&Bs[b_r][b_c]) = *(const float4*)(Bb + (size_t)(k0 + b_r) * N + b_c);
        __syncthreads();
        #pragma unroll
        for (int kk = 0; kk < 8; kk++) {
            float ar[8], br[8];
            *(float4*)(ar)     = *(float4*)(&As[kk][tr * 8]);
            *(float4*)(ar + 4) = *(float4*)(&As[kk][tr * 8 + 4]);
            *(float4*)(br)     = *(float4*)(&Bs[kk][tc * 8]);
            *(float4*)(br + 4) = *(float4*)(&Bs[kk][tc * 8 + 4]);
            #pragma unroll
            for (int i = 0; i < 8; i++)
                #pragma unroll
                for (int j = 0; j < 8; j++)
                    acc[i][j] = fmaf(ar[i], br[j], acc[i][j]);
        }
        __syncthreads();
    }
    #pragma unroll
    for (int i = 0; i < 8; i++) {
        float* Cp = C + (size_t)(by * 128 + tr * 8 + i) * N + bx * 128 + tc * 8;
        float4 c0 = make_float4(acc[i][0], acc[i][1], acc[i][2], acc[i][3]);
        float4 c1 = make_float4(acc[i][4], acc[i][5], acc[i][6], acc[i][7]);
        *(float4*)(Cp)     = c0;
        *(float4*)(Cp + 4) = c1;
    }
}

// ---------------- RoPE: in-place rotate q and k -----------------------
__global__ __launch_bounds__(256) void rope_k(float* __restrict__ q,
                                              float* __restrict__ k,
                                              const int* __restrict__ pos_ids)
{
    int idx = blockIdx.x * blockDim.x + threadIdx.x;
    const int total = B_ * S_ * (H_ + HKV_) * (DH_ / 2);
    if (idx >= total) return;
    int i = idx & 63; idx >>= 6;
    int head = idx % (H_ + HKV_); idx /= (H_ + HKV_);
    int s = idx % S_;
    int b = idx / S_;
    float pos = (float)pos_ids[b * S_ + s];
    float invf = powf(10000.0f, -(float)i / 64.0f);
    float sn, cs;
    sincosf(pos * invf, &sn, &cs);
    float* base;
    if (head < H_)
        base = q + ((size_t)(b * S_ + s) * H_ + head) * DH_;
    else
        base = k + ((size_t)(b * S_ + s) * HKV_ + (head - H_)) * DH_;
    float x1 = base[i], x2 = base[i + 64];
    base[i]      = x1 * cs - x2 * sn;
    base[i + 64] = x2 * cs + x1 * sn;
}

// ---------------- Flash attention, causal, fp32 -----------------------
#define FM  64
#define FN  64
#define FNP 65
#define FD  128
#define FLASH_SMEM ((FM*FD + FD*FNP + FN*FD + FM*FNP) * 4)

__global__ __launch_bounds__(256) void flash_k(const float* __restrict__ Q,
                                               const float* __restrict__ K,
                                               const float* __restrict__ V,
                                               float* __restrict__ O)
{
    extern __shared__ float sm[];
    float* Qs  = sm;                 // [FM][FD]
    float* Kst = Qs + FM * FD;       // [FD][FNP]  (transposed K tile, odd pad)
    float* Vs  = Kst + FD * FNP;     // [FN][FD]
    float* Ps  = Vs + FN * FD;       // [FM][FNP]

    const int m0 = blockIdx.x * FM;
    const int h  = blockIdx.y;
    const int b  = blockIdx.z;
    const int hkv = h / NREP_;
    const int tid = threadIdx.x;
    const int tx = tid & 15, ty = tid >> 4;
    const float scale = 0.08838834764831845f; // 1/sqrt(128)

    // load Q tile (pre-scaled)
    for (int i = tid; i < FM * FD / 4; i += 256) {
        int r = i >> 5;
        int c4 = (i & 31) * 4;
        float4 v = *(const float4*)(Q + ((size_t)(b * S_ + m0 + r) * H_ + h) * DH_ + c4);
        v.x *= scale; v.y *= scale; v.z *= scale; v.w *= scale;
        *(float4*)(Qs + r * FD + c4) = v;
    }

    float m_i[4], l_i[4], acc[4][8];
    #pragma unroll
    for (int r = 0; r < 4; r++) {
        m_i[r] = -1e30f; l_i[r] = 0.f;
        #pragma unroll
        for (int c = 0; c < 8; c++) acc[r][c] = 0.f;
    }

    for (int n0 = 0; n0 <= m0; n0 += FN) {
        __syncthreads();  // protect Kst/Vs/Ps from prev iter; Qs ready on first
        // K tile, transposed, scalar loads (coalesced gmem, conflict-free STS:
        // bank = (kk + r) mod 32, kk consecutive across lanes)
        for (int i = tid; i < FN * FD; i += 256) {
            int kk = i & 127;
            int r  = i >> 7;
            Kst[kk * FNP + r] =
                K[((size_t)(b * S_ + n0 + r) * HKV_ + hkv) * DH_ + kk];
        }
        // V tile row-major
        for (int i = tid; i < FN * FD / 4; i += 256) {
            int r = i >> 5;
            int c4 = (i & 31) * 4;
            *(float4*)(Vs + r * FD + c4) =
                *(const float4*)(V + ((size_t)(b * S_ + n0 + r) * HKV_ + hkv) * DH_ + c4);
        }
        __syncthreads();

        // scores: thread owns rows ty*4..+3, cols tx + 16*c (strided, scalar LDS;
        // bank = (kk + tx + 16c) mod 32 -> conflict-free across the 16 tx lanes)
        float s[4][4];
        #pragma unroll
        for (int r = 0; r < 4; r++)
            #pragma unroll
            for (int c = 0; c < 4; c++) s[r][c] = 0.f;

        #pragma unroll 4
        for (int kk = 0; kk < FD; kk++) {
            float qv[4];
            #pragma unroll
            for (int r = 0; r < 4; r++) qv[r] = Qs[(ty * 4 + r) * FD + kk];
            float kv[4];
            #pragma unroll
            for (int c = 0; c < 4; c++) kv[c] = Kst[kk * FNP + tx + 16 * c];
            #pragma unroll
            for (int r = 0; r < 4; r++)
                #pragma unroll
                for (int c = 0; c < 4; c++)
                    s[r][c] = fmaf(qv[r], kv[c], s[r][c]);
        }

        // causal mask (only the diagonal tile needs it)
        if (n0 >= m0) {
            #pragma unroll
            for (int r = 0; r < 4; r++)
                #pragma unroll
                for (int c = 0; c < 4; c++)
                    if (n0 + tx + 16 * c > m0 + ty * 4 + r) s[r][c] = -1e30f;
        }

        // online softmax (xor masks 1/2/4/8 reduce across the 16 tx lanes)
        #pragma unroll
        for (int r = 0; r < 4; r++) {
            float rm = fmaxf(fmaxf(s[r][0], s[r][1]), fmaxf(s[r][2], s[r][3]));
            #pragma unroll
            for (int msk = 8; msk; msk >>= 1)
                rm = fmaxf(rm, __shfl_xor_sync(0xffffffffu, rm, msk));
            float mn = fmaxf(m_i[r], rm);
            float alpha = __expf(m_i[r] - mn);
            float ps[4], rs = 0.f;
            #pragma unroll
            for (int c = 0; c < 4; c++) { ps[c] = __expf(s[r][c] - mn); rs += ps[c]; }
            #pragma unroll
            for (int msk = 8; msk; msk >>= 1)
                rs += __shfl_xor_sync(0xffffffffu, rs, msk);
            l_i[r] = l_i[r] * alpha + rs;
            m_i[r] = mn;
            #pragma unroll
            for (int c = 0; c < 8; c++) acc[r][c] *= alpha;
            #pragma unroll
            for (int c = 0; c < 4; c++)
                Ps[(ty * 4 + r) * FNP + tx + 16 * c] = ps[c];
        }
        __syncthreads();

        // acc += P[64,64] @ V[64,128]; thread owns rows ty*4..+3, cols tx*8..+7
        #pragma unroll 2
        for (int j = 0; j < FN; j++) {
            float pr[4];
            #pragma unroll
            for (int r = 0; r < 4; r++) pr[r] = Ps[(ty * 4 + r) * FNP + j];
            float4 v0 = *(float4*)(Vs + j * FD + tx * 8);
            float4 v1 = *(float4*)(Vs + j * FD + tx * 8 + 4);
            #pragma unroll
            for (int r = 0; r < 4; r++) {
                acc[r][0] = fmaf(pr[r], v0.x, acc[r][0]);
                acc[r][1] = fmaf(pr[r], v0.y, acc[r][1]);
                acc[r][2] = fmaf(pr[r], v0.z, acc[r][2]);
                acc[r][3] = fmaf(pr[r], v0.w, acc[r][3]);
                acc[r][4] = fmaf(pr[r], v1.x, acc[r][4]);
                acc[r][5] = fmaf(pr[r], v1.y, acc[r][5]);
                acc[r][6] = fmaf(pr[r], v1.z, acc[r][6]);
                acc[r][7] = fmaf(pr[r], v1.w, acc[r][7]);
            }
        }
    }

    // epilogue: normalize and store
    #pragma unroll
    for (int r = 0; r < 4; r++) {
        float inv = 1.0f / l_i[r];
        float* Op = O + ((size_t)(b * S_ + m0 + ty * 4 + r) * H_ + h) * DH_ + tx * 8;
        float4 o0 = make_float4(acc[r][0] * inv, acc[r][1] * inv,
                                acc[r][2] * inv, acc[r][3] * inv);
        float4 o1 = make_float4(acc[r][4] * inv, acc[r][5] * inv,
                                acc[r][6] * inv, acc[r][7] * inv);
        *(float4*)(Op)     = o0;
        *(float4*)(Op + 4) = o1;
    }
}

extern "C" void kernel_launch(void* const* d_in, const int* in_sizes, int n_in,
                              void* d_out, int out_size)
{
    const float* x   = (const float*)d_in[0];
    const int*   pos = (const int*)  d_in[1];
    const float* wq  = (const float*)d_in[2];
    const float* wk  = (const float*)d_in[3];
    const float* wv  = (const float*)d_in[4];
    const float* wo  = (const float*)d_in[5];
    float* out = (float*)d_out;

    float *q, *k, *v, *o;
    cudaGetSymbolAddress((void**)&q, g_q);
    cudaGetSymbolAddress((void**)&k, g_k);
    cudaGetSymbolAddress((void**)&v, g_v);
    cudaGetSymbolAddress((void**)&o, g_o);

    cudaFuncSetAttribute(flash_k, cudaFuncAttributeMaxDynamicSharedMemorySize,
                         FLASH_SMEM);

    // QKV projections
    sgemm_k<<<dim3((H_*DH_)/128, BS_/128), 256>>>(x, wq, q, BS_, H_*DH_, D_);
    sgemm_k<<<dim3((HKV_*DH_)/128, BS_/128), 256>>>(x, wk, k, BS_, HKV_*DH_, D_);
    sgemm_k<<<dim3((HKV_*DH_)/128, BS_/128), 256>>>(x, wv, v, BS_, HKV_*DH_, D_);

    // RoPE (in place on q, k)
    {
        int total = B_ * S_ * (H_ + HKV_) * (DH_ / 2);
        rope_k<<<(total + 255) / 256, 256>>>(q, k, pos);
    }

    // Causal flash attention
    flash_k<<<dim3(S_/FM, H_, B_), 256, FLASH_SMEM>>>(q, k, v, o);

    // Output projection
    sgemm_k<<<dim3(D_/128, BS_/128), 256>>>(o, wo, out, BS_, D_, D_);
}

// round 3
// speedup vs baseline: 1.0341x; 1.0341x over previous
#include <cuda_runtime.h>
#include <math.h>

#define B_    2
#define S_    2048
#define D_    2048
#define H_    16
#define HKV_  4
#define DH_   128
#define NREP_ (H_/HKV_)
#define BS_   (B_*S_)

typedef unsigned long long ull;

// ---- packed f32x2 helpers (sm_100+) ----
__device__ __forceinline__ ull ffma2(ull a, ull b, ull c) {
    ull d;
    asm("fma.rn.f32x2 %0, %1, %2, %3;" : "=l"(d) : "l"(a), "l"(b), "l"(c));
    return d;
}
__device__ __forceinline__ ull fmul2(ull a, ull b) {
    ull d;
    asm("mul.rn.f32x2 %0, %1, %2;" : "=l"(d) : "l"(a), "l"(b));
    return d;
}
__device__ __forceinline__ ull dup2(float x) {
    ull d; unsigned u = __float_as_uint(x);
    asm("mov.b64 %0, {%1, %2};" : "=l"(d) : "r"(u), "r"(u));
    return d;
}
__device__ __forceinline__ ull pk2(float lo, float hi) {
    ull d;
    asm("mov.b64 %0, {%1, %2};" : "=l"(d)
        : "r"(__float_as_uint(lo)), "r"(__float_as_uint(hi)));
    return d;
}
__device__ __forceinline__ float2 unpk2(ull v) {
    unsigned lo, hi;
    asm("mov.b64 {%0, %1}, %2;" : "=r"(lo), "=r"(hi) : "l"(v));
    return make_float2(__uint_as_float(lo), __uint_as_float(hi));
}

// Scratch (static device allocations; no cudaMalloc allowed)
__device__ float g_q[BS_*H_*DH_];    // [B,S,H,DH]
__device__ float g_k[BS_*HKV_*DH_];  // [B,S,HKV,DH]
__device__ float g_v[BS_*HKV_*DH_];
__device__ float g_o[BS_*H_*DH_];    // attention out, [B,S,H*DH]

// ---------------- SGEMM: C[M,N] = A[M,K] @ B[K,N], all row-major ----------
// 128x128 tile, BK=8, 256 threads, 8x8 microtile, f32x2 packed FMA.
__global__ __launch_bounds__(256) void sgemm_k(const float* __restrict__ A,
                                               const float* __restrict__ Bm,
                                               float* __restrict__ C,
                                               int M, int N, int K)
{
    __shared__ __align__(16) float As[8][128];
    __shared__ __align__(16) float Bs[8][128];
    const int bx = blockIdx.x, by = blockIdx.y;
    const int tid = threadIdx.x;
    const int tr = tid >> 4, tc = tid & 15;

    const float* Ab = A + (size_t)by * 128 * K;
    const float* Bb = Bm + (size_t)bx * 128;

    ull acc2[8][4];
    #pragma unroll
    for (int i = 0; i < 8; i++)
        #pragma unroll
        for (int j = 0; j < 4; j++) acc2[i][j] = 0ull;

    const int a_r = tid >> 1, a_c = (tid & 1) * 4;
    const int b_r = tid >> 5, b_c = (tid & 31) * 4;

    for (int k0 = 0; k0 < K; k0 += 8) {
        float4 av = *(const float4*)(Ab + (size_t)a_r * K + k0 + a_c);
        As[a_c + 0][a_r] = av.x;
        As[a_c + 1][a_r] = av.y;
        As[a_c + 2][a_r] = av.z;
        As[a_c + 3][a_r] = av.w;
        *(float4*)(&Bs[b_r][b_c]) = *(const float4*)(Bb + (size_t)(k0 + b_r) * N + b_c);
        __syncthreads();
        #pragma unroll
        for (int kk = 0; kk < 8; kk++) {
            float ar[8];
            *(float4*)(ar)     = *(float4*)(&As[kk][tr * 8]);
            *(float4*)(ar + 4) = *(float4*)(&As[kk][tr * 8 + 4]);
            const ull* Bp = (const ull*)(&Bs[kk][tc * 8]);
            ull b0 = Bp[0], b1 = Bp[1], b2 = Bp[2], b3 = Bp[3];
            #pragma unroll
            for (int i = 0; i < 8; i++) {
                ull aa = dup2(ar[i]);
                acc2[i][0] = ffma2(aa, b0, acc2[i][0]);
                acc2[i][1] = ffma2(aa, b1, acc2[i][1]);
                acc2[i][2] = ffma2(aa, b2, acc2[i][2]);
                acc2[i][3] = ffma2(aa, b3, acc2[i][3]);
            }
        }
        __syncthreads();
    }
    #pragma unroll
    for (int i = 0; i < 8; i++) {
        float* Cp = C + (size_t)(by * 128 + tr * 8 + i) * N + bx * 128 + tc * 8;
        float2 p0 = unpk2(acc2[i][0]);
        float2 p1 = unpk2(acc2[i][1]);
        float2 p2 = unpk2(acc2[i][2]);
        float2 p3 = unpk2(acc2[i][3]);
        *(float4*)(Cp)     = make_float4(p0.x, p0.y, p1.x, p1.y);
        *(float4*)(Cp + 4) = make_float4(p2.x, p2.y, p3.x, p3.y);
    }
}

// ---------------- RoPE: in-place rotate q and k -----------------------
__global__ __launch_bounds__(256) void rope_k(float* __restrict__ q,
                                              float* __restrict__ k,
                                              const int* __restrict__ pos_ids)
{
    int idx = blockIdx.x * blockDim.x + threadIdx.x;
    const int total = B_ * S_ * (H_ + HKV_) * (DH_ / 2);
    if (idx >= total) return;
    int i = idx & 63; idx >>= 6;
    int head = idx % (H_ + HKV_); idx /= (H_ + HKV_);
    int s = idx % S_;
    int b = idx / S_;
    float pos = (float)pos_ids[b * S_ + s];
    float invf = powf(10000.0f, -(float)i / 64.0f);
    float sn, cs;
    sincosf(pos * invf, &sn, &cs);
    float* base;
    if (head < H_)
        base = q + ((size_t)(b * S_ + s) * H_ + head) * DH_;
    else
        base = k + ((size_t)(b * S_ + s) * HKV_ + (head - H_)) * DH_;
    float x1 = base[i], x2 = base[i + 64];
    base[i]      = x1 * cs - x2 * sn;
    base[i + 64] = x2 * cs + x1 * sn;
}

// ---------------- Flash attention, causal, fp32 + f32x2 ----------------
#define FM  64
#define FN  64
#define FNP 65
#define FD  128
#define FLASH_SMEM ((FM*FD + FD*FNP + FN*FD + FM*FNP) * 4)

__global__ __launch_bounds__(256) void flash_k(const float* __restrict__ Q,
                                               const float* __restrict__ K,
                                               const float* __restrict__ V,
                                               float* __restrict__ O)
{
    extern __shared__ float sm[];
    float* Qs  = sm;                 // [FM][FD]
    float* Kst = Qs + FM * FD;       // [FD][FNP]  (transposed K tile, odd pad)
    float* Vs  = Kst + FD * FNP;     // [FN][FD]
    float* Ps  = Vs + FN * FD;       // [FM][FNP]

    const int m0 = blockIdx.x * FM;
    const int h  = blockIdx.y;
    const int b  = blockIdx.z;
    const int hkv = h / NREP_;
    const int tid = threadIdx.x;
    const int tx = tid & 15, ty = tid >> 4;
    const float scale = 0.08838834764831845f; // 1/sqrt(128)

    // load Q tile (pre-scaled)
    for (int i = tid; i < FM * FD / 4; i += 256) {
        int r = i >> 5;
        int c4 = (i & 31) * 4;
        float4 v = *(const float4*)(Q + ((size_t)(b * S_ + m0 + r) * H_ + h) * DH_ + c4);
        v.x *= scale; v.y *= scale; v.z *= scale; v.w *= scale;
        *(float4*)(Qs + r * FD + c4) = v;
    }

    float m_i[4], l_i[4];
    ull acc2[4][4];   // rows ty*4+r, col pairs tx*8 + {0,1},{2,3},{4,5},{6,7}
    #pragma unroll
    for (int r = 0; r < 4; r++) {
        m_i[r] = -1e30f; l_i[r] = 0.f;
        #pragma unroll
        for (int c = 0; c < 4; c++) acc2[r][c] = 0ull;
    }

    for (int n0 = 0; n0 <= m0; n0 += FN) {
        __syncthreads();  // protect Kst/Vs/Ps from prev iter; Qs ready on first
        // K tile, transposed, scalar stores (coalesced gmem, conflict-free STS)
        for (int i = tid; i < FN * FD; i += 256) {
            int kk = i & 127;
            int r  = i >> 7;
            Kst[kk * FNP + r] =
                K[((size_t)(b * S_ + n0 + r) * HKV_ + hkv) * DH_ + kk];
        }
        // V tile row-major
        for (int i = tid; i < FN * FD / 4; i += 256) {
            int r = i >> 5;
            int c4 = (i & 31) * 4;
            *(float4*)(Vs + r * FD + c4) =
                *(const float4*)(V + ((size_t)(b * S_ + n0 + r) * HKV_ + hkv) * DH_ + c4);
        }
        __syncthreads();

        // scores: rows ty*4+r, cols tx + 16*c (c=0..3), packed in c pairs
        ull s2[4][2];
        #pragma unroll
        for (int r = 0; r < 4; r++) { s2[r][0] = 0ull; s2[r][1] = 0ull; }

        #pragma unroll 4
        for (int kk = 0; kk < FD; kk++) {
            float qv[4];
            #pragma unroll
            for (int r = 0; r < 4; r++) qv[r] = Qs[(ty * 4 + r) * FD + kk];
            const float* Kp = Kst + kk * FNP + tx;
            ull k01 = pk2(Kp[0],  Kp[16]);
            ull k23 = pk2(Kp[32], Kp[48]);
            #pragma unroll
            for (int r = 0; r < 4; r++) {
                ull qq = dup2(qv[r]);
                s2[r][0] = ffma2(qq, k01, s2[r][0]);
                s2[r][1] = ffma2(qq, k23, s2[r][1]);
            }
        }

        // unpack scores to scalars
        float s[4][4];
        #pragma unroll
        for (int r = 0; r < 4; r++) {
            float2 a = unpk2(s2[r][0]), c = unpk2(s2[r][1]);
            s[r][0] = a.x; s[r][1] = a.y; s[r][2] = c.x; s[r][3] = c.y;
        }

        // causal mask (only the diagonal tile needs it)
        if (n0 >= m0) {
            #pragma unroll
            for (int r = 0; r < 4; r++)
                #pragma unroll
                for (int c = 0; c < 4; c++)
                    if (n0 + tx + 16 * c > m0 + ty * 4 + r) s[r][c] = -1e30f;
        }

        // online softmax (xor masks 1/2/4/8 reduce across the 16 tx lanes)
        #pragma unroll
        for (int r = 0; r < 4; r++) {
            float rm = fmaxf(fmaxf(s[r][0], s[r][1]), fmaxf(s[r][2], s[r][3]));
            #pragma unroll
            for (int msk = 8; msk; msk >>= 1)
                rm = fmaxf(rm, __shfl_xor_sync(0xffffffffu, rm, msk));
            float mn = fmaxf(m_i[r], rm);
            float alpha = __expf(m_i[r] - mn);
            float ps[4], rs = 0.f;
            #pragma unroll
            for (int c = 0; c < 4; c++) { ps[c] = __expf(s[r][c] - mn); rs += ps[c]; }
            #pragma unroll
            for (int msk = 8; msk; msk >>= 1)
                rs += __shfl_xor_sync(0xffffffffu, rs, msk);
            l_i[r] = l_i[r] * alpha + rs;
            m_i[r] = mn;
            ull aa = dup2(alpha);
            #pragma unroll
            for (int c = 0; c < 4; c++) acc2[r][c] = fmul2(acc2[r][c], aa);
            #pragma unroll
            for (int c = 0; c < 4; c++)
                Ps[(ty * 4 + r) * FNP + tx + 16 * c] = ps[c];
        }
        __syncthreads();

        // acc += P[64,64] @ V[64,128]; packed column pairs
        #pragma unroll 2
        for (int j = 0; j < FN; j++) {
            float pr[4];
            #pragma unroll
            for (int r = 0; r < 4; r++) pr[r] = Ps[(ty * 4 + r) * FNP + j];
            const ull* Vp = (const ull*)(Vs + j * FD + tx * 8);
            ull v0 = Vp[0], v1 = Vp[1], v2 = Vp[2], v3 = Vp[3];
            #pragma unroll
            for (int r = 0; r < 4; r++) {
                ull pp = dup2(pr[r]);
                acc2[r][0] = ffma2(pp, v0, acc2[r][0]);
                acc2[r][1] = ffma2(pp, v1, acc2[r][1]);
                acc2[r][2] = ffma2(pp, v2, acc2[r][2]);
                acc2[r][3] = ffma2(pp, v3, acc2[r][3]);
            }
        }
    }

    // epilogue: normalize and store
    #pragma unroll
    for (int r = 0; r < 4; r++) {
        float inv = 1.0f / l_i[r];
        float* Op = O + ((size_t)(b * S_ + m0 + ty * 4 + r) * H_ + h) * DH_ + tx * 8;
        float2 p0 = unpk2(acc2[r][0]);
        float2 p1 = unpk2(acc2[r][1]);
        float2 p2 = unpk2(acc2[r][2]);
        float2 p3 = unpk2(acc2[r][3]);
        *(float4*)(Op)     = make_float4(p0.x * inv, p0.y * inv, p1.x * inv, p1.y * inv);
        *(float4*)(Op + 4) = make_float4(p2.x * inv, p2.y * inv, p3.x * inv, p3.y * inv);
    }
}

extern "C" void kernel_launch(void* const* d_in, const int* in_sizes, int n_in,
                              void* d_out, int out_size)
{
    const float* x   = (const float*)d_in[0];
    const int*   pos = (const int*)  d_in[1];
    const float* wq  = (const float*)d_in[2];
    const float* wk  = (const float*)d_in[3];
    const float* wv  = (const float*)d_in[4];
    const float* wo  = (const float*)d_in[5];
    float* out = (float*)d_out;

    float *q, *k, *v, *o;
    cudaGetSymbolAddress((void**)&q, g_q);
    cudaGetSymbolAddress((void**)&k, g_k);
    cudaGetSymbolAddress((void**)&v, g_v);
    cudaGetSymbolAddress((void**)&o, g_o);

    cudaFuncSetAttribute(flash_k, cudaFuncAttributeMaxDynamicSharedMemorySize,
                         FLASH_SMEM);

    // QKV projections
    sgemm_k<<<dim3((H_*DH_)/128, BS_/128), 256>>>(x, wq, q, BS_, H_*DH_, D_);
    sgemm_k<<<dim3((HKV_*DH_)/128, BS_/128), 256>>>(x, wk, k, BS_, HKV_*DH_, D_);
    sgemm_k<<<dim3((HKV_*DH_)/128, BS_/128), 256>>>(x, wv, v, BS_, HKV_*DH_, D_);

    // RoPE (in place on q, k)
    {
        int total = B_ * S_ * (H_ + HKV_) * (DH_ / 2);
        rope_k<<<(total + 255) / 256, 256>>>(q, k, pos);
    }

    // Causal flash attention
    flash_k<<<dim3(S_/FM, H_, B_), 256, FLASH_SMEM>>>(q, k, v, o);

    // Output projection
    sgemm_k<<<dim3(D_/128, BS_/128), 256>>>(o, wo, out, BS_, D_, D_);
}

// round 4
// speedup vs baseline: 1.7282x; 1.6712x over previous
#include <cuda_runtime.h>
#include <cuda_bf16.h>
#include <math.h>
#include <stdint.h>

#define B_    2
#define S_    2048
#define D_    2048
#define H_    16
#define HKV_  4
#define DH_   128
#define NREP_ (H_/HKV_)
#define BS_   (B_*S_)

typedef unsigned long long ull;

// ---- packed f32x2 helpers (used by flash) ----
__device__ __forceinline__ ull ffma2(ull a, ull b, ull c) {
    ull d;
    asm("fma.rn.f32x2 %0, %1, %2, %3;" : "=l"(d) : "l"(a), "l"(b), "l"(c));
    return d;
}
__device__ __forceinline__ ull fmul2(ull a, ull b) {
    ull d;
    asm("mul.rn.f32x2 %0, %1, %2;" : "=l"(d) : "l"(a), "l"(b));
    return d;
}
__device__ __forceinline__ ull dup2(float x) {
    ull d; unsigned u = __float_as_uint(x);
    asm("mov.b64 %0, {%1, %2};" : "=l"(d) : "r"(u), "r"(u));
    return d;
}
__device__ __forceinline__ ull pk2(float lo, float hi) {
    ull d;
    asm("mov.b64 %0, {%1, %2};" : "=l"(d)
        : "r"(__float_as_uint(lo)), "r"(__float_as_uint(hi)));
    return d;
}
__device__ __forceinline__ float2 unpk2(ull v) {
    unsigned lo, hi;
    asm("mov.b64 {%0, %1}, %2;" : "=r"(lo), "=r"(hi) : "l"(v));
    return make_float2(__uint_as_float(lo), __uint_as_float(hi));
}

// ---------------- scratch (static device allocations) ------------------
__device__ float g_q[BS_*H_*DH_];
__device__ float g_k[BS_*HKV_*DH_];
__device__ float g_v[BS_*HKV_*DH_];
__device__ float g_o[BS_*H_*DH_];

__device__ __nv_bfloat16 g_xh[BS_*D_],  g_xl[BS_*D_];
__device__ __nv_bfloat16 g_oh[BS_*H_*DH_], g_ol[BS_*H_*DH_];
__device__ __nv_bfloat16 g_wqh[(H_*DH_)*D_],  g_wql[(H_*DH_)*D_];   // [N][K]
__device__ __nv_bfloat16 g_wkh[(HKV_*DH_)*D_], g_wkl[(HKV_*DH_)*D_];
__device__ __nv_bfloat16 g_wvh[(HKV_*DH_)*D_], g_wvl[(HKV_*DH_)*D_];
__device__ __nv_bfloat16 g_woh[D_*(H_*DH_)],  g_wol[D_*(H_*DH_)];

// ---------------- fp32 -> bf16 hi/lo split (same layout) ---------------
__global__ __launch_bounds__(256) void split_k(const float* __restrict__ in,
                                               __nv_bfloat16* __restrict__ hi,
                                               __nv_bfloat16* __restrict__ lo,
                                               int n)
{
    int i = blockIdx.x * 256 + threadIdx.x;
    if (i < n) {
        float v = in[i];
        __nv_bfloat16 h = __float2bfloat16_rn(v);
        hi[i] = h;
        lo[i] = __float2bfloat16_rn(v - __bfloat162float(h));
    }
}

// ---------------- fp32 [K][N] -> bf16 hi/lo transposed [N][K] ----------
__global__ __launch_bounds__(256) void splitT_k(const float* __restrict__ w,
                                                __nv_bfloat16* __restrict__ th,
                                                __nv_bfloat16* __restrict__ tl,
                                                int K, int N)
{
    __shared__ float t[32][33];
    const int bx = blockIdx.x, by = blockIdx.y;
    const int tx = threadIdx.x, ty = threadIdx.y;   // 32 x 8
    #pragma unroll
    for (int j = 0; j < 4; j++)
        t[ty + j * 8][tx] = w[(size_t)(by * 32 + ty + j * 8) * N + bx * 32 + tx];
    __syncthreads();
    #pragma unroll
    for (int j = 0; j < 4; j++) {
        int n  = bx * 32 + ty + j * 8;
        int kc = by * 32 + tx;
        float v = t[tx][ty + j * 8];
        __nv_bfloat16 h = __float2bfloat16_rn(v);
        th[(size_t)n * K + kc] = h;
        tl[(size_t)n * K + kc] = __float2bfloat16_rn(v - __bfloat162float(h));
    }
}

// ---------------- bf16-split tensor-core GEMM --------------------------
// C[M,N](fp32) = A[M,K] @ Bt[N,K]^T, A/B given as hi+lo bf16 pairs.
// CTA tile 128x128, BK=32, 8 warps (2x4), warp tile 64x32, m16n8k16.
#define LDB 40                       // smem row pitch in halves (20 words)
#define TILE_HALVES (128*LDB)        // one 128x32 tile (padded)
#define TILE_BYTES  (TILE_HALVES*2)

__device__ __forceinline__ void cp16(void* smem, const void* gmem) {
    uint32_t s = (uint32_t)__cvta_generic_to_shared(smem);
    asm volatile("cp.async.cg.shared.global [%0], [%1], 16;" :: "r"(s), "l"(gmem));
}
__device__ __forceinline__ void mma16816(float* c, const uint32_t* a, const uint32_t* b) {
    asm volatile("mma.sync.aligned.m16n8k16.row.col.f32.bf16.bf16.f32 "
        "{%0,%1,%2,%3}, {%4,%5,%6,%7}, {%8,%9}, {%0,%1,%2,%3};"
        : "+f"(c[0]), "+f"(c[1]), "+f"(c[2]), "+f"(c[3])
        : "r"(a[0]), "r"(a[1]), "r"(a[2]), "r"(a[3]), "r"(b[0]), "r"(b[1]));
}

__global__ __launch_bounds__(256) void gemm_bf16(const __nv_bfloat16* __restrict__ Ah,
                                                 const __nv_bfloat16* __restrict__ Al,
                                                 const __nv_bfloat16* __restrict__ Bh,
                                                 const __nv_bfloat16* __restrict__ Bl,
                                                 float* __restrict__ C,
                                                 int M, int N, int K)
{
    extern __shared__ char smem_raw[];
    // stage layout: AsH | AsL | BtH | BtL, each TILE_BYTES; two stages
    const int tid  = threadIdx.x;
    const int lane = tid & 31, warp = tid >> 5;
    const int wm = warp >> 2, wn = warp & 3;
    const int aRow0 = blockIdx.y * 128;
    const int bRow0 = blockIdx.x * 128;

    float acc[4][4][4];
    #pragma unroll
    for (int mi = 0; mi < 4; mi++)
        #pragma unroll
        for (int ni = 0; ni < 4; ni++)
            #pragma unroll
            for (int e = 0; e < 4; e++) acc[mi][ni][e] = 0.f;

    const int nchunk = K / 32;

    // prologue: async-load chunk 0 into stage 0
    {
        char* stg = smem_raw;
        __nv_bfloat16* AsH = (__nv_bfloat16*)stg;
        __nv_bfloat16* AsL = AsH + TILE_HALVES;
        __nv_bfloat16* BtH = AsL + TILE_HALVES;
        __nv_bfloat16* BtL = BtH + TILE_HALVES;
        #pragma unroll
        for (int s = tid; s < 512; s += 256) {
            int row = s >> 2, kg = (s & 3) * 8;
            size_t ga = (size_t)(aRow0 + row) * K + kg;
            size_t gb = (size_t)(bRow0 + row) * K + kg;
            cp16(&AsH[row * LDB + kg], Ah + ga);
            cp16(&AsL[row * LDB + kg], Al + ga);
            cp16(&BtH[row * LDB + kg], Bh + gb);
            cp16(&BtL[row * LDB + kg], Bl + gb);
        }
        asm volatile("cp.async.commit_group;" ::: "memory");
    }

    for (int c = 0; c < nchunk; c++) {
        char* cur = smem_raw + (c & 1) * 4 * TILE_BYTES;
        char* nxt = smem_raw + ((c + 1) & 1) * 4 * TILE_BYTES;

        if (c + 1 < nchunk) {
            int k0 = (c + 1) * 32;
            __nv_bfloat16* AsH = (__nv_bfloat16*)nxt;
            __nv_bfloat16* AsL = AsH + TILE_HALVES;
            __nv_bfloat16* BtH = AsL + TILE_HALVES;
            __nv_bfloat16* BtL = BtH + TILE_HALVES;
            #pragma unroll
            for (int s = tid; s < 512; s += 256) {
                int row = s >> 2, kg = (s & 3) * 8;
                size_t ga = (size_t)(aRow0 + row) * K + k0 + kg;
                size_t gb = (size_t)(bRow0 + row) * K + k0 + kg;
                cp16(&AsH[row * LDB + kg], Ah + ga);
                cp16(&AsL[row * LDB + kg], Al + ga);
                cp16(&BtH[row * LDB + kg], Bh + gb);
                cp16(&BtL[row * LDB + kg], Bl + gb);
            }
            asm volatile("cp.async.commit_group;" ::: "memory");
            asm volatile("cp.async.wait_group 1;" ::: "memory");
        } else {
            asm volatile("cp.async.wait_group 0;" ::: "memory");
        }
        __syncthreads();

        const __nv_bfloat16* AsH = (const __nv_bfloat16*)cur;
        const __nv_bfloat16* AsL = AsH + TILE_HALVES;
        const __nv_bfloat16* BtH = AsL + TILE_HALVES;
        const __nv_bfloat16* BtL = BtH + TILE_HALVES;

        #pragma unroll
        for (int ks = 0; ks < 32; ks += 16) {
            const int ar = wm * 64 + (lane >> 2);
            const int br = wn * 32 + (lane >> 2);
            const int kq = ks + (lane & 3) * 2;

            uint32_t ah[4][4], al[4][4], bh[4][2], bl[4][2];
            #pragma unroll
            for (int mi = 0; mi < 4; mi++) {
                int r0 = (ar + mi * 16) * LDB;
                int r1 = (ar + mi * 16 + 8) * LDB;
                ah[mi][0] = *(const uint32_t*)&AsH[r0 + kq];
                ah[mi][1] = *(const uint32_t*)&AsH[r1 + kq];
                ah[mi][2] = *(const uint32_t*)&AsH[r0 + kq + 8];
                ah[mi][3] = *(const uint32_t*)&AsH[r1 + kq + 8];
                al[mi][0] = *(const uint32_t*)&AsL[r0 + kq];
                al[mi][1] = *(const uint32_t*)&AsL[r1 + kq];
                al[mi][2] = *(const uint32_t*)&AsL[r0 + kq + 8];
                al[mi][3] = *(const uint32_t*)&AsL[r1 + kq + 8];
            }
            #pragma unroll
            for (int ni = 0; ni < 4; ni++) {
                int r = (br + ni * 8) * LDB;
                bh[ni][0] = *(const uint32_t*)&BtH[r + kq];
                bh[ni][1] = *(const uint32_t*)&BtH[r + kq + 8];
                bl[ni][0] = *(const uint32_t*)&BtL[r + kq];
                bl[ni][1] = *(const uint32_t*)&BtL[r + kq + 8];
            }
            #pragma unroll
            for (int mi = 0; mi < 4; mi++)
                #pragma unroll
                for (int ni = 0; ni < 4; ni++) {
                    mma16816(acc[mi][ni], ah[mi], bh[ni]);
                    mma16816(acc[mi][ni], ah[mi], bl[ni]);
                    mma16816(acc[mi][ni], al[mi], bh[ni]);
                }
        }
        __syncthreads();
    }

    // epilogue
    #pragma unroll
    for (int mi = 0; mi < 4; mi++)
        #pragma unroll
        for (int ni = 0; ni < 4; ni++) {
            int row = aRow0 + wm * 64 + mi * 16 + (lane >> 2);
            int col = bRow0 + wn * 32 + ni * 8 + (lane & 3) * 2;
            *(float2*)&C[(size_t)row * N + col] =
                make_float2(acc[mi][ni][0], acc[mi][ni][1]);
            *(float2*)&C[(size_t)(row + 8) * N + col] =
                make_float2(acc[mi][ni][2], acc[mi][ni][3]);
        }
}

// ---------------- RoPE: in-place rotate q and k -----------------------
__global__ __launch_bounds__(256) void rope_k(float* __restrict__ q,
                                              float* __restrict__ k,
                                              const int* __restrict__ pos_ids)
{
    int idx = blockIdx.x * blockDim.x + threadIdx.x;
    const int total = B_ * S_ * (H_ + HKV_) * (DH_ / 2);
    if (idx >= total) return;
    int i = idx & 63; idx >>= 6;
    int head = idx % (H_ + HKV_); idx /= (H_ + HKV_);
    int s = idx % S_;
    int b = idx / S_;
    float pos = (float)pos_ids[b * S_ + s];
    float invf = powf(10000.0f, -(float)i / 64.0f);
    float sn, cs;
    sincosf(pos * invf, &sn, &cs);
    float* base;
    if (head < H_)
        base = q + ((size_t)(b * S_ + s) * H_ + head) * DH_;
    else
        base = k + ((size_t)(b * S_ + s) * HKV_ + (head - H_)) * DH_;
    float x1 = base[i], x2 = base[i + 64];
    base[i]      = x1 * cs - x2 * sn;
    base[i + 64] = x2 * cs + x1 * sn;
}

// ---------------- Flash attention, causal, fp32 + f32x2 ----------------
#define FM  64
#define FN  64
#define FNP 65
#define FD  128
#define FLASH_SMEM ((FM*FD + FD*FNP + FN*FD + FM*FNP) * 4)

__global__ __launch_bounds__(256) void flash_k(const float* __restrict__ Q,
                                               const float* __restrict__ K,
                                               const float* __restrict__ V,
                                               float* __restrict__ O)
{
    extern __shared__ float sm[];
    float* Qs  = sm;
    float* Kst = Qs + FM * FD;
    float* Vs  = Kst + FD * FNP;
    float* Ps  = Vs + FN * FD;

    const int m0 = blockIdx.x * FM;
    const int h  = blockIdx.y;
    const int b  = blockIdx.z;
    const int hkv = h / NREP_;
    const int tid = threadIdx.x;
    const int tx = tid & 15, ty = tid >> 4;
    const float scale = 0.08838834764831845f;

    for (int i = tid; i < FM * FD / 4; i += 256) {
        int r = i >> 5;
        int c4 = (i & 31) * 4;
        float4 v = *(const float4*)(Q + ((size_t)(b * S_ + m0 + r) * H_ + h) * DH_ + c4);
        v.x *= scale; v.y *= scale; v.z *= scale; v.w *= scale;
        *(float4*)(Qs + r * FD + c4) = v;
    }

    float m_i[4], l_i[4];
    ull acc2[4][4];
    #pragma unroll
    for (int r = 0; r < 4; r++) {
        m_i[r] = -1e30f; l_i[r] = 0.f;
        #pragma unroll
        for (int c = 0; c < 4; c++) acc2[r][c] = 0ull;
    }

    for (int n0 = 0; n0 <= m0; n0 += FN) {
        __syncthreads();
        for (int i = tid; i < FN * FD; i += 256) {
            int kk = i & 127;
            int r  = i >> 7;
            Kst[kk * FNP + r] =
                K[((size_t)(b * S_ + n0 + r) * HKV_ + hkv) * DH_ + kk];
        }
        for (int i = tid; i < FN * FD / 4; i += 256) {
            int r = i >> 5;
            int c4 = (i & 31) * 4;
            *(float4*)(Vs + r * FD + c4) =
                *(const float4*)(V + ((size_t)(b * S_ + n0 + r) * HKV_ + hkv) * DH_ + c4);
        }
        __syncthreads();

        ull s2[4][2];
        #pragma unroll
        for (int r = 0; r < 4; r++) { s2[r][0] = 0ull; s2[r][1] = 0ull; }

        #pragma unroll 4
        for (int kk = 0; kk < FD; kk++) {
            float qv[4];
            #pragma unroll
            for (int r = 0; r < 4; r++) qv[r] = Qs[(ty * 4 + r) * FD + kk];
            const float* Kp = Kst + kk * FNP + tx;
            ull k01 = pk2(Kp[0],  Kp[16]);
            ull k23 = pk2(Kp[32], Kp[48]);
            #pragma unroll
            for (int r = 0; r < 4; r++) {
                ull qq = dup2(qv[r]);
                s2[r][0] = ffma2(qq, k01, s2[r][0]);
                s2[r][1] = ffma2(qq, k23, s2[r][1]);
            }
        }

        float s[4][4];
        #pragma unroll
        for (int r = 0; r < 4; r++) {
            float2 a = unpk2(s2[r][0]), c = unpk2(s2[r][1]);
            s[r][0] = a.x; s[r][1] = a.y; s[r][2] = c.x; s[r][3] = c.y;
        }

        if (n0 >= m0) {
            #pragma unroll
            for (int r = 0; r < 4; r++)
                #pragma unroll
                for (int c = 0; c < 4; c++)
                    if (n0 + tx + 16 * c > m0 + ty * 4 + r) s[r][c] = -1e30f;
        }

        #pragma unroll
        for (int r = 0; r < 4; r++) {
            float rm = fmaxf(fmaxf(s[r][0], s[r][1]), fmaxf(s[r][2], s[r][3]));
            #pragma unroll
            for (int msk = 8; msk; msk >>= 1)
                rm = fmaxf(rm, __shfl_xor_sync(0xffffffffu, rm, msk));
            float mn = fmaxf(m_i[r], rm);
            float alpha = __expf(m_i[r] - mn);
            float ps[4], rs = 0.f;
            #pragma unroll
            for (int c = 0; c < 4; c++) { ps[c] = __expf(s[r][c] - mn); rs += ps[c]; }
            #pragma unroll
            for (int msk = 8; msk; msk >>= 1)
                rs += __shfl_xor_sync(0xffffffffu, rs, msk);
            l_i[r] = l_i[r] * alpha + rs;
            m_i[r] = mn;
            ull aa = dup2(alpha);
            #pragma unroll
            for (int c = 0; c < 4; c++) acc2[r][c] = fmul2(acc2[r][c], aa);
            #pragma unroll
            for (int c = 0; c < 4; c++)
                Ps[(ty * 4 + r) * FNP + tx + 16 * c] = ps[c];
        }
        __syncthreads();

        #pragma unroll 2
        for (int j = 0; j < FN; j++) {
            float pr[4];
            #pragma unroll
            for (int r = 0; r < 4; r++) pr[r] = Ps[(ty * 4 + r) * FNP + j];
            const ull* Vp = (const ull*)(Vs + j * FD + tx * 8);
            ull v0 = Vp[0], v1 = Vp[1], v2 = Vp[2], v3 = Vp[3];
            #pragma unroll
            for (int r = 0; r < 4; r++) {
                ull pp = dup2(pr[r]);
                acc2[r][0] = ffma2(pp, v0, acc2[r][0]);
                acc2[r][1] = ffma2(pp, v1, acc2[r][1]);
                acc2[r][2] = ffma2(pp, v2, acc2[r][2]);
                acc2[r][3] = ffma2(pp, v3, acc2[r][3]);
            }
        }
    }

    #pragma unroll
    for (int r = 0; r < 4; r++) {
        float inv = 1.0f / l_i[r];
        float* Op = O + ((size_t)(b * S_ + m0 + ty * 4 + r) * H_ + h) * DH_ + tx * 8;
        float2 p0 = unpk2(acc2[r][0]);
        float2 p1 = unpk2(acc2[r][1]);
        float2 p2 = unpk2(acc2[r][2]);
        float2 p3 = unpk2(acc2[r][3]);
        *(float4*)(Op)     = make_float4(p0.x * inv, p0.y * inv, p1.x * inv, p1.y * inv);
        *(float4*)(Op + 4) = make_float4(p2.x * inv, p2.y * inv, p3.x * inv, p3.y * inv);
    }
}

extern "C" void kernel_launch(void* const* d_in, const int* in_sizes, int n_in,
                              void* d_out, int out_size)
{
    const float* x   = (const float*)d_in[0];
    const int*   pos = (const int*)  d_in[1];
    const float* wq  = (const float*)d_in[2];
    const float* wk  = (const float*)d_in[3];
    const float* wv  = (const float*)d_in[4];
    const float* wo  = (const float*)d_in[5];
    float* out = (float*)d_out;

    float *q, *k, *v, *o;
    cudaGetSymbolAddress((void**)&q, g_q);
    cudaGetSymbolAddress((void**)&k, g_k);
    cudaGetSymbolAddress((void**)&v, g_v);
    cudaGetSymbolAddress((void**)&o, g_o);

    __nv_bfloat16 *xh, *xl, *oh, *ol, *wqh, *wql, *wkh, *wkl, *wvh, *wvl, *woh, *wol;
    cudaGetSymbolAddress((void**)&xh,  g_xh);  cudaGetSymbolAddress((void**)&xl,  g_xl);
    cudaGetSymbolAddress((void**)&oh,  g_oh);  cudaGetSymbolAddress((void**)&ol,  g_ol);
    cudaGetSymbolAddress((void**)&wqh, g_wqh); cudaGetSymbolAddress((void**)&wql, g_wql);
    cudaGetSymbolAddress((void**)&wkh, g_wkh); cudaGetSymbolAddress((void**)&wkl, g_wkl);
    cudaGetSymbolAddress((void**)&wvh, g_wvh); cudaGetSymbolAddress((void**)&wvl, g_wvl);
    cudaGetSymbolAddress((void**)&woh, g_woh); cudaGetSymbolAddress((void**)&wol, g_wol);

    cudaFuncSetAttribute(flash_k, cudaFuncAttributeMaxDynamicSharedMemorySize,
                         FLASH_SMEM);
    cudaFuncSetAttribute(gemm_bf16, cudaFuncAttributeMaxDynamicSharedMemorySize,
                         8 * TILE_BYTES);

    // split inputs / weights (weights transposed to [N][K])
    split_k<<<(BS_*D_ + 255)/256, 256>>>(x, xh, xl, BS_*D_);
    splitT_k<<<dim3((H_*DH_)/32,  D_/32), dim3(32,8)>>>(wq, wqh, wql, D_, H_*DH_);
    splitT_k<<<dim3((HKV_*DH_)/32, D_/32), dim3(32,8)>>>(wk, wkh, wkl, D_, HKV_*DH_);
    splitT_k<<<dim3((HKV_*DH_)/32, D_/32), dim3(32,8)>>>(wv, wvh, wvl, D_, HKV_*DH_);
    splitT_k<<<dim3(D_/32, (H_*DH_)/32), dim3(32,8)>>>(wo, woh, wol, H_*DH_, D_);

    // QKV projections (tensor core)
    gemm_bf16<<<dim3((H_*DH_)/128,  BS_/128), 256, 8*TILE_BYTES>>>(xh, xl, wqh, wql, q, BS_, H_*DH_,  D_);
    gemm_bf16<<<dim3((HKV_*DH_)/128, BS_/128), 256, 8*TILE_BYTES>>>(xh, xl, wkh, wkl, k, BS_, HKV_*DH_, D_);
    gemm_bf16<<<dim3((HKV_*DH_)/128, BS_/128), 256, 8*TILE_BYTES>>>(xh, xl, wvh, wvl, v, BS_, HKV_*DH_, D_);

    // RoPE (in place on q, k)
    {
        int total = B_ * S_ * (H_ + HKV_) * (DH_ / 2);
        rope_k<<<(total + 255) / 256, 256>>>(q, k, pos);
    }

    // Causal flash attention
    flash_k<<<dim3(S_/FM, H_, B_), 256, FLASH_SMEM>>>(q, k, v, o);

    // Output projection (tensor core)
    split_k<<<(BS_*H_*DH_ + 255)/256, 256>>>(o, oh, ol, BS_*H_*DH_);
    gemm_bf16<<<dim3(D_/128, BS_/128), 256, 8*TILE_BYTES>>>(oh, ol, woh, wol, out, BS_, D_, D_);
}

// round 5
// speedup vs baseline: 3.0380x; 1.7579x over previous
#include <cuda_runtime.h>
#include <cuda_bf16.h>
#include <math.h>
#include <stdint.h>

#define B_    2
#define S_    2048
#define D_    2048
#define H_    16
#define HKV_  4
#define DH_   128
#define NREP_ (H_/HKV_)
#define BS_   (B_*S_)

// ---------------- scratch (static device allocations) ------------------
__device__ float g_q[BS_*H_*DH_];      // [b][s][h][dh] fp32 from gemm
__device__ float g_k[BS_*HKV_*DH_];
__device__ float g_v[BS_*HKV_*DH_];

__device__ __nv_bfloat16 g_xh[BS_*D_],  g_xl[BS_*D_];
__device__ __nv_bfloat16 g_oh[BS_*H_*DH_], g_ol[BS_*H_*DH_];
__device__ __nv_bfloat16 g_wqh[(H_*DH_)*D_],  g_wql[(H_*DH_)*D_];   // [N][K]
__device__ __nv_bfloat16 g_wkh[(HKV_*DH_)*D_], g_wkl[(HKV_*DH_)*D_];
__device__ __nv_bfloat16 g_wvh[(HKV_*DH_)*D_], g_wvl[(HKV_*DH_)*D_];
__device__ __nv_bfloat16 g_woh[D_*(H_*DH_)],  g_wol[D_*(H_*DH_)];

// head-major bf16 hi/lo Q/K/V for flash
__device__ __nv_bfloat16 g_fqh[(size_t)B_*H_*S_*DH_],   g_fql[(size_t)B_*H_*S_*DH_];
__device__ __nv_bfloat16 g_fkh[(size_t)B_*HKV_*S_*DH_], g_fkl[(size_t)B_*HKV_*S_*DH_];
__device__ __nv_bfloat16 g_fvh[(size_t)B_*HKV_*S_*DH_], g_fvl[(size_t)B_*HKV_*S_*DH_];

// ---------------- common helpers ---------------------------------------
__device__ __forceinline__ void cp16(void* smem, const void* gmem) {
    uint32_t s = (uint32_t)__cvta_generic_to_shared(smem);
    asm volatile("cp.async.cg.shared.global [%0], [%1], 16;" :: "r"(s), "l"(gmem));
}
__device__ __forceinline__ void mma16816(float* c, const uint32_t* a, const uint32_t* b) {
    asm volatile("mma.sync.aligned.m16n8k16.row.col.f32.bf16.bf16.f32 "
        "{%0,%1,%2,%3}, {%4,%5,%6,%7}, {%8,%9}, {%0,%1,%2,%3};"
        : "+f"(c[0]), "+f"(c[1]), "+f"(c[2]), "+f"(c[3])
        : "r"(a[0]), "r"(a[1]), "r"(a[2]), "r"(a[3]), "r"(b[0]), "r"(b[1]));
}
__device__ __forceinline__ void ldmx4t(uint32_t* r, uint32_t addr) {
    asm volatile("ldmatrix.sync.aligned.m8n8.x4.trans.shared.b16 {%0,%1,%2,%3}, [%4];"
        : "=r"(r[0]), "=r"(r[1]), "=r"(r[2]), "=r"(r[3]) : "r"(addr));
}
__device__ __forceinline__ void pack_hl(float a, float b, uint32_t& hi, uint32_t& lo) {
    __nv_bfloat162 h2 = __floats2bfloat162_rn(a, b);
    hi = *(uint32_t*)&h2;
    __nv_bfloat162 l2 = __floats2bfloat162_rn(a - __bfloat162float(h2.x),
                                              b - __bfloat162float(h2.y));
    lo = *(uint32_t*)&l2;
}

// ---------------- fp32 -> bf16 hi/lo split (same layout) ---------------
__global__ __launch_bounds__(256) void split_k(const float* __restrict__ in,
                                               __nv_bfloat16* __restrict__ hi,
                                               __nv_bfloat16* __restrict__ lo,
                                               int n)
{
    int i = blockIdx.x * 256 + threadIdx.x;
    if (i < n) {
        float v = in[i];
        __nv_bfloat16 h = __float2bfloat16_rn(v);
        hi[i] = h;
        lo[i] = __float2bfloat16_rn(v - __bfloat162float(h));
    }
}

// ---------------- fp32 [K][N] -> bf16 hi/lo transposed [N][K] ----------
__global__ __launch_bounds__(256) void splitT_k(const float* __restrict__ w,
                                                __nv_bfloat16* __restrict__ th,
                                                __nv_bfloat16* __restrict__ tl,
                                                int K, int N)
{
    __shared__ float t[32][33];
    const int bx = blockIdx.x, by = blockIdx.y;
    const int tx = threadIdx.x, ty = threadIdx.y;   // 32 x 8
    #pragma unroll
    for (int j = 0; j < 4; j++)
        t[ty + j * 8][tx] = w[(size_t)(by * 32 + ty + j * 8) * N + bx * 32 + tx];
    __syncthreads();
    #pragma unroll
    for (int j = 0; j < 4; j++) {
        int n  = bx * 32 + ty + j * 8;
        int kc = by * 32 + tx;
        float v = t[tx][ty + j * 8];
        __nv_bfloat16 h = __float2bfloat16_rn(v);
        th[(size_t)n * K + kc] = h;
        tl[(size_t)n * K + kc] = __float2bfloat16_rn(v - __bfloat162float(h));
    }
}

// ---------------- bf16-split tensor-core GEMM --------------------------
#define LDB 40
#define TILE_HALVES (128*LDB)
#define TILE_BYTES  (TILE_HALVES*2)

__global__ __launch_bounds__(256) void gemm_bf16(const __nv_bfloat16* __restrict__ Ah,
                                                 const __nv_bfloat16* __restrict__ Al,
                                                 const __nv_bfloat16* __restrict__ Bh,
                                                 const __nv_bfloat16* __restrict__ Bl,
                                                 float* __restrict__ C,
                                                 int M, int N, int K)
{
    extern __shared__ char smem_raw[];
    const int tid  = threadIdx.x;
    const int lane = tid & 31, warp = tid >> 5;
    const int wm = warp >> 2, wn = warp & 3;
    const int aRow0 = blockIdx.y * 128;
    const int bRow0 = blockIdx.x * 128;

    float acc[4][4][4];
    #pragma unroll
    for (int mi = 0; mi < 4; mi++)
        #pragma unroll
        for (int ni = 0; ni < 4; ni++)
            #pragma unroll
            for (int e = 0; e < 4; e++) acc[mi][ni][e] = 0.f;

    const int nchunk = K / 32;

    {
        char* stg = smem_raw;
        __nv_bfloat16* AsH = (__nv_bfloat16*)stg;
        __nv_bfloat16* AsL = AsH + TILE_HALVES;
        __nv_bfloat16* BtH = AsL + TILE_HALVES;
        __nv_bfloat16* BtL = BtH + TILE_HALVES;
        #pragma unroll
        for (int s = tid; s < 512; s += 256) {
            int row = s >> 2, kg = (s & 3) * 8;
            size_t ga = (size_t)(aRow0 + row) * K + kg;
            size_t gb = (size_t)(bRow0 + row) * K + kg;
            cp16(&AsH[row * LDB + kg], Ah + ga);
            cp16(&AsL[row * LDB + kg], Al + ga);
            cp16(&BtH[row * LDB + kg], Bh + gb);
            cp16(&BtL[row * LDB + kg], Bl + gb);
        }
        asm volatile("cp.async.commit_group;" ::: "memory");
    }

    for (int c = 0; c < nchunk; c++) {
        char* cur = smem_raw + (c & 1) * 4 * TILE_BYTES;
        char* nxt = smem_raw + ((c + 1) & 1) * 4 * TILE_BYTES;

        if (c + 1 < nchunk) {
            int k0 = (c + 1) * 32;
            __nv_bfloat16* AsH = (__nv_bfloat16*)nxt;
            __nv_bfloat16* AsL = AsH + TILE_HALVES;
            __nv_bfloat16* BtH = AsL + TILE_HALVES;
            __nv_bfloat16* BtL = BtH + TILE_HALVES;
            #pragma unroll
            for (int s = tid; s < 512; s += 256) {
                int row = s >> 2, kg = (s & 3) * 8;
                size_t ga = (size_t)(aRow0 + row) * K + k0 + kg;
                size_t gb = (size_t)(bRow0 + row) * K + k0 + kg;
                cp16(&AsH[row * LDB + kg], Ah + ga);
                cp16(&AsL[row * LDB + kg], Al + ga);
                cp16(&BtH[row * LDB + kg], Bh + gb);
                cp16(&BtL[row * LDB + kg], Bl + gb);
            }
            asm volatile("cp.async.commit_group;" ::: "memory");
            asm volatile("cp.async.wait_group 1;" ::: "memory");
        } else {
            asm volatile("cp.async.wait_group 0;" ::: "memory");
        }
        __syncthreads();

        const __nv_bfloat16* AsH = (const __nv_bfloat16*)cur;
        const __nv_bfloat16* AsL = AsH + TILE_HALVES;
        const __nv_bfloat16* BtH = AsL + TILE_HALVES;
        const __nv_bfloat16* BtL = BtH + TILE_HALVES;

        #pragma unroll
        for (int ks = 0; ks < 32; ks += 16) {
            const int ar = wm * 64 + (lane >> 2);
            const int br = wn * 32 + (lane >> 2);
            const int kq = ks + (lane & 3) * 2;

            uint32_t ah[4][4], al[4][4], bh[4][2], bl[4][2];
            #pragma unroll
            for (int mi = 0; mi < 4; mi++) {
                int r0 = (ar + mi * 16) * LDB;
                int r1 = (ar + mi * 16 + 8) * LDB;
                ah[mi][0] = *(const uint32_t*)&AsH[r0 + kq];
                ah[mi][1] = *(const uint32_t*)&AsH[r1 + kq];
                ah[mi][2] = *(const uint32_t*)&AsH[r0 + kq + 8];
                ah[mi][3] = *(const uint32_t*)&AsH[r1 + kq + 8];
                al[mi][0] = *(const uint32_t*)&AsL[r0 + kq];
                al[mi][1] = *(const uint32_t*)&AsL[r1 + kq];
                al[mi][2] = *(const uint32_t*)&AsL[r0 + kq + 8];
                al[mi][3] = *(const uint32_t*)&AsL[r1 + kq + 8];
            }
            #pragma unroll
            for (int ni = 0; ni < 4; ni++) {
                int r = (br + ni * 8) * LDB;
                bh[ni][0] = *(const uint32_t*)&BtH[r + kq];
                bh[ni][1] = *(const uint32_t*)&BtH[r + kq + 8];
                bl[ni][0] = *(const uint32_t*)&BtL[r + kq];
                bl[ni][1] = *(const uint32_t*)&BtL[r + kq + 8];
            }
            #pragma unroll
            for (int mi = 0; mi < 4; mi++)
                #pragma unroll
                for (int ni = 0; ni < 4; ni++) {
                    mma16816(acc[mi][ni], ah[mi], bh[ni]);
                    mma16816(acc[mi][ni], ah[mi], bl[ni]);
                    mma16816(acc[mi][ni], al[mi], bh[ni]);
                }
        }
        __syncthreads();
    }

    #pragma unroll
    for (int mi = 0; mi < 4; mi++)
        #pragma unroll
        for (int ni = 0; ni < 4; ni++) {
            int row = aRow0 + wm * 64 + mi * 16 + (lane >> 2);
            int col = bRow0 + wn * 32 + ni * 8 + (lane & 3) * 2;
            *(float2*)&C[(size_t)row * N + col] =
                make_float2(acc[mi][ni][0], acc[mi][ni][1]);
            *(float2*)&C[(size_t)(row + 8) * N + col] =
                make_float2(acc[mi][ni][2], acc[mi][ni][3]);
        }
}

// ---------- RoPE + scale + split + relayout for Q and K ----------------
__global__ __launch_bounds__(256) void ropesplit_qk(
    const float* __restrict__ q, const float* __restrict__ k,
    const int* __restrict__ pos,
    __nv_bfloat16* __restrict__ qh, __nv_bfloat16* __restrict__ ql,
    __nv_bfloat16* __restrict__ kh, __nv_bfloat16* __restrict__ kl)
{
    int idx = blockIdx.x * 256 + threadIdx.x;
    const int total = B_ * S_ * (H_ + HKV_) * 64;
    if (idx >= total) return;
    int i = idx & 63; idx >>= 6;
    int head = idx % (H_ + HKV_); idx /= (H_ + HKV_);
    int s = idx % S_;
    int b = idx / S_;
    float p = (float)pos[b * S_ + s];
    float invf = powf(10000.0f, -(float)i / 64.0f);
    float sn, cs;
    sincosf(p * invf, &sn, &cs);
    const float scale = 0.08838834764831845f;   // 1/sqrt(128)

    if (head < H_) {
        const float* src = q + ((size_t)(b * S_ + s) * H_ + head) * DH_;
        float x1 = src[i], x2 = src[i + 64];
        float y1 = (x1 * cs - x2 * sn) * scale;
        float y2 = (x2 * cs + x1 * sn) * scale;
        size_t dst = ((size_t)(b * H_ + head) * S_ + s) * DH_;
        __nv_bfloat16 h1 = __float2bfloat16_rn(y1);
        __nv_bfloat16 h2 = __float2bfloat16_rn(y2);
        qh[dst + i]      = h1;
        ql[dst + i]      = __float2bfloat16_rn(y1 - __bfloat162float(h1));
        qh[dst + i + 64] = h2;
        ql[dst + i + 64] = __float2bfloat16_rn(y2 - __bfloat162float(h2));
    } else {
        int hk = head - H_;
        const float* src = k + ((size_t)(b * S_ + s) * HKV_ + hk) * DH_;
        float x1 = src[i], x2 = src[i + 64];
        float y1 = x1 * cs - x2 * sn;
        float y2 = x2 * cs + x1 * sn;
        size_t dst = ((size_t)(b * HKV_ + hk) * S_ + s) * DH_;
        __nv_bfloat16 h1 = __float2bfloat16_rn(y1);
        __nv_bfloat16 h2 = __float2bfloat16_rn(y2);
        kh[dst + i]      = h1;
        kl[dst + i]      = __float2bfloat16_rn(y1 - __bfloat162float(h1));
        kh[dst + i + 64] = h2;
        kl[dst + i + 64] = __float2bfloat16_rn(y2 - __bfloat162float(h2));
    }
}

// ---------- V split + relayout -----------------------------------------
__global__ __launch_bounds__(256) void split_v(const float* __restrict__ v,
                                               __nv_bfloat16* __restrict__ vh,
                                               __nv_bfloat16* __restrict__ vl)
{
    int idx = blockIdx.x * 256 + threadIdx.x;
    const int total = B_ * S_ * HKV_ * DH_;
    if (idx >= total) return;
    int d = idx & 127; int t = idx >> 7;
    int hk = t % HKV_; t /= HKV_;
    int s = t % S_; int b = t / S_;
    float x = v[((size_t)(b * S_ + s) * HKV_ + hk) * DH_ + d];
    size_t dst = ((size_t)(b * HKV_ + hk) * S_ + s) * DH_ + d;
    __nv_bfloat16 h = __float2bfloat16_rn(x);
    vh[dst] = h;
    vl[dst] = __float2bfloat16_rn(x - __bfloat162float(h));
}

// ---------------- tensor-core flash attention --------------------------
// 128 threads (4 warps), 64 q-rows per CTA, key tiles of 64, DH=128.
#define FP   136                            // smem pitch (halves): 68 words, conflict-free
#define FLASH_SMEM (4 * 64 * FP * 2)        // Kh,Kl,Vh,Vl

__global__ __launch_bounds__(128) void flash_tc(
    const __nv_bfloat16* __restrict__ qh, const __nv_bfloat16* __restrict__ ql,
    const __nv_bfloat16* __restrict__ kh, const __nv_bfloat16* __restrict__ kl,
    const __nv_bfloat16* __restrict__ vh, const __nv_bfloat16* __restrict__ vl,
    __nv_bfloat16* __restrict__ oh, __nv_bfloat16* __restrict__ ol)
{
    extern __shared__ __nv_bfloat16 smh[];
    __nv_bfloat16* Kh_s = smh;
    __nv_bfloat16* Kl_s = Kh_s + 64 * FP;
    __nv_bfloat16* Vh_s = Kl_s + 64 * FP;
    __nv_bfloat16* Vl_s = Vh_s + 64 * FP;

    const int m0 = blockIdx.x * 64;
    const int h  = blockIdx.y, b = blockIdx.z;
    const int hkv = h / NREP_;
    const int tid = threadIdx.x, lane = tid & 31, warp = tid >> 5;

    const size_t qbase = ((size_t)(b * H_ + h) * S_ + m0) * DH_;
    const size_t kvb   = ((size_t)(b * HKV_ + hkv) * S_) * DH_;

    // ---- stage Q tile (reuse V region), build register A-fragments ----
    for (int i = tid; i < 1024; i += 128) {
        int r = i >> 4, ck = (i & 15) << 3;
        cp16(&Vh_s[r * FP + ck], qh + qbase + r * DH_ + ck);
        cp16(&Vl_s[r * FP + ck], ql + qbase + r * DH_ + ck);
    }
    asm volatile("cp.async.commit_group;\ncp.async.wait_group 0;" ::: "memory");
    __syncthreads();

    uint32_t qfh[8][4], qfl[8][4];
    {
        int r0 = warp * 16 + (lane >> 2);
        int kq = (lane & 3) * 2;
        #pragma unroll
        for (int c = 0; c < 8; c++) {
            int o0 = r0 * FP + c * 16 + kq;
            int o1 = (r0 + 8) * FP + c * 16 + kq;
            qfh[c][0] = *(uint32_t*)&Vh_s[o0];
            qfh[c][1] = *(uint32_t*)&Vh_s[o1];
            qfh[c][2] = *(uint32_t*)&Vh_s[o0 + 8];
            qfh[c][3] = *(uint32_t*)&Vh_s[o1 + 8];
            qfl[c][0] = *(uint32_t*)&Vl_s[o0];
            qfl[c][1] = *(uint32_t*)&Vl_s[o1];
            qfl[c][2] = *(uint32_t*)&Vl_s[o0 + 8];
            qfl[c][3] = *(uint32_t*)&Vl_s[o1 + 8];
        }
    }
    __syncthreads();

    float acc[16][4];
    #pragma unroll
    for (int nj = 0; nj < 16; nj++)
        #pragma unroll
        for (int e = 0; e < 4; e++) acc[nj][e] = 0.f;
    float m_i[2] = {-1e30f, -1e30f}, l_i[2] = {0.f, 0.f};

    for (int n0 = 0; n0 <= m0; n0 += 64) {
        // load K,V tiles (hi+lo)
        for (int i = tid; i < 1024; i += 128) {
            int r = i >> 4, ck = (i & 15) << 3;
            size_t g = kvb + (size_t)(n0 + r) * DH_ + ck;
            cp16(&Kh_s[r * FP + ck], kh + g);
            cp16(&Kl_s[r * FP + ck], kl + g);
            cp16(&Vh_s[r * FP + ck], vh + g);
            cp16(&Vl_s[r * FP + ck], vl + g);
        }
        asm volatile("cp.async.commit_group;\ncp.async.wait_group 0;" ::: "memory");
        __syncthreads();

        // ---- scores: 16x64 per warp via 3-way split MMA ----
        float sf[8][4];
        #pragma unroll
        for (int j = 0; j < 8; j++)
            #pragma unroll
            for (int e = 0; e < 4; e++) sf[j][e] = 0.f;

        #pragma unroll
        for (int c = 0; c < 8; c++) {
            #pragma unroll
            for (int j = 0; j < 8; j++) {
                int base = (j * 8 + (lane >> 2)) * FP + c * 16 + (lane & 3) * 2;
                uint32_t bhf[2] = { *(uint32_t*)&Kh_s[base], *(uint32_t*)&Kh_s[base + 8] };
                uint32_t blf[2] = { *(uint32_t*)&Kl_s[base], *(uint32_t*)&Kl_s[base + 8] };
                mma16816(sf[j], qfh[c], bhf);
                mma16816(sf[j], qfh[c], blf);
                mma16816(sf[j], qfl[c], bhf);
            }
        }

        // ---- causal mask (diagonal tile only) ----
        if (n0 == m0) {
            int r0 = m0 + warp * 16 + (lane >> 2);
            #pragma unroll
            for (int j = 0; j < 8; j++)
                #pragma unroll
                for (int e = 0; e < 4; e++) {
                    int col = n0 + j * 8 + (lane & 3) * 2 + (e & 1);
                    int row = r0 + ((e >> 1) << 3);
                    if (col > row) sf[j][e] = -1e30f;
                }
        }

        // ---- online softmax (per row-half; quad = lanes xor 1,2) ----
        #pragma unroll
        for (int rh = 0; rh < 2; rh++) {
            float mx = -1e30f;
            #pragma unroll
            for (int j = 0; j < 8; j++)
                mx = fmaxf(mx, fmaxf(sf[j][2 * rh], sf[j][2 * rh + 1]));
            mx = fmaxf(mx, __shfl_xor_sync(0xffffffffu, mx, 1));
            mx = fmaxf(mx, __shfl_xor_sync(0xffffffffu, mx, 2));
            float mn = fmaxf(m_i[rh], mx);
            float alpha = __expf(m_i[rh] - mn);
            float rs = 0.f;
            #pragma unroll
            for (int j = 0; j < 8; j++) {
                sf[j][2 * rh]     = __expf(sf[j][2 * rh] - mn);
                sf[j][2 * rh + 1] = __expf(sf[j][2 * rh + 1] - mn);
                rs += sf[j][2 * rh] + sf[j][2 * rh + 1];
            }
            rs += __shfl_xor_sync(0xffffffffu, rs, 1);
            rs += __shfl_xor_sync(0xffffffffu, rs, 2);
            l_i[rh] = l_i[rh] * alpha + rs;
            m_i[rh] = mn;
            #pragma unroll
            for (int nj = 0; nj < 16; nj++) {
                acc[nj][2 * rh]     *= alpha;
                acc[nj][2 * rh + 1] *= alpha;
            }
        }

        // ---- P -> bf16 hi/lo A-fragments (register-only reshape) ----
        uint32_t ph[4][4], pl[4][4];
        #pragma unroll
        for (int kc = 0; kc < 4; kc++) {
            pack_hl(sf[2*kc][0],   sf[2*kc][1],   ph[kc][0], pl[kc][0]);
            pack_hl(sf[2*kc][2],   sf[2*kc][3],   ph[kc][1], pl[kc][1]);
            pack_hl(sf[2*kc+1][0], sf[2*kc+1][1], ph[kc][2], pl[kc][2]);
            pack_hl(sf[2*kc+1][2], sf[2*kc+1][3], ph[kc][3], pl[kc][3]);
        }

        // ---- acc += P @ V  (V^T fragments via ldmatrix.trans) ----
        int g  = lane >> 3, rr = lane & 7;
        #pragma unroll
        for (int kc = 0; kc < 4; kc++) {
            int vrow = kc * 16 + rr + ((g & 1) << 3);
            #pragma unroll
            for (int nj = 0; nj < 16; nj += 2) {
                int vcol = (nj + (g >> 1)) * 8;
                uint32_t ah = (uint32_t)__cvta_generic_to_shared(&Vh_s[vrow * FP + vcol]);
                uint32_t al = (uint32_t)__cvta_generic_to_shared(&Vl_s[vrow * FP + vcol]);
                uint32_t vbh[4], vbl[4];
                ldmx4t(vbh, ah);
                ldmx4t(vbl, al);
                mma16816(acc[nj],     ph[kc], vbh);
                mma16816(acc[nj],     ph[kc], vbl);
                mma16816(acc[nj],     pl[kc], vbh);
                mma16816(acc[nj + 1], ph[kc], vbh + 2);
                mma16816(acc[nj + 1], ph[kc], vbl + 2);
                mma16816(acc[nj + 1], pl[kc], vbh + 2);
            }
        }
        __syncthreads();   // protect smem before next iteration's loads
    }

    // ---- epilogue: normalize, split to bf16 hi/lo, store [b][s][h*dh] ----
    float inv0 = 1.0f / l_i[0], inv1 = 1.0f / l_i[1];
    int r0 = m0 + warp * 16 + (lane >> 2);
    size_t rowA = ((size_t)(b * S_ + r0)) * (H_ * DH_) + h * DH_;
    #pragma unroll
    for (int nj = 0; nj < 16; nj++) {
        int cc = nj * 8 + (lane & 3) * 2;
        float v0 = acc[nj][0] * inv0, v1 = acc[nj][1] * inv0;
        float v2 = acc[nj][2] * inv1, v3 = acc[nj][3] * inv1;
        __nv_bfloat162 h01 = __floats2bfloat162_rn(v0, v1);
        __nv_bfloat162 l01 = __floats2bfloat162_rn(v0 - __bfloat162float(h01.x),
                                                   v1 - __bfloat162float(h01.y));
        *(__nv_bfloat162*)&oh[rowA + cc] = h01;
        *(__nv_bfloat162*)&ol[rowA + cc] = l01;
        __nv_bfloat162 h23 = __floats2bfloat162_rn(v2, v3);
        __nv_bfloat162 l23 = __floats2bfloat162_rn(v2 - __bfloat162float(h23.x),
                                                   v3 - __bfloat162float(h23.y));
        *(__nv_bfloat162*)&oh[rowA + (size_t)8 * (H_ * DH_) + cc] = h23;
        *(__nv_bfloat162*)&ol[rowA + (size_t)8 * (H_ * DH_) + cc] = l23;
    }
}

extern "C" void kernel_launch(void* const* d_in, const int* in_sizes, int n_in,
                              void* d_out, int out_size)
{
    const float* x   = (const float*)d_in[0];
    const int*   pos = (const int*)  d_in[1];
    const float* wq  = (const float*)d_in[2];
    const float* wk  = (const float*)d_in[3];
    const float* wv  = (const float*)d_in[4];
    const float* wo  = (const float*)d_in[5];
    float* out = (float*)d_out;

    float *q, *k, *v;
    cudaGetSymbolAddress((void**)&q, g_q);
    cudaGetSymbolAddress((void**)&k, g_k);
    cudaGetSymbolAddress((void**)&v, g_v);

    __nv_bfloat16 *xh, *xl, *oh, *ol, *wqh, *wql, *wkh, *wkl, *wvh, *wvl, *woh, *wol;
    cudaGetSymbolAddress((void**)&xh,  g_xh);  cudaGetSymbolAddress((void**)&xl,  g_xl);
    cudaGetSymbolAddress((void**)&oh,  g_oh);  cudaGetSymbolAddress((void**)&ol,  g_ol);
    cudaGetSymbolAddress((void**)&wqh, g_wqh); cudaGetSymbolAddress((void**)&wql, g_wql);
    cudaGetSymbolAddress((void**)&wkh, g_wkh); cudaGetSymbolAddress((void**)&wkl, g_wkl);
    cudaGetSymbolAddress((void**)&wvh, g_wvh); cudaGetSymbolAddress((void**)&wvl, g_wvl);
    cudaGetSymbolAddress((void**)&woh, g_woh); cudaGetSymbolAddress((void**)&wol, g_wol);

    __nv_bfloat16 *fqh, *fql, *fkh, *fkl, *fvh, *fvl;
    cudaGetSymbolAddress((void**)&fqh, g_fqh); cudaGetSymbolAddress((void**)&fql, g_fql);
    cudaGetSymbolAddress((void**)&fkh, g_fkh); cudaGetSymbolAddress((void**)&fkl, g_fkl);
    cudaGetSymbolAddress((void**)&fvh, g_fvh); cudaGetSymbolAddress((void**)&fvl, g_fvl);

    cudaFuncSetAttribute(gemm_bf16, cudaFuncAttributeMaxDynamicSharedMemorySize,
                         8 * TILE_BYTES);
    cudaFuncSetAttribute(flash_tc, cudaFuncAttributeMaxDynamicSharedMemorySize,
                         FLASH_SMEM);

    // splits
    split_k<<<(BS_*D_ + 255)/256, 256>>>(x, xh, xl, BS_*D_);
    splitT_k<<<dim3((H_*DH_)/32,  D_/32), dim3(32,8)>>>(wq, wqh, wql, D_, H_*DH_);
    splitT_k<<<dim3((HKV_*DH_)/32, D_/32), dim3(32,8)>>>(wk, wkh, wkl, D_, HKV_*DH_);
    splitT_k<<<dim3((HKV_*DH_)/32, D_/32), dim3(32,8)>>>(wv, wvh, wvl, D_, HKV_*DH_);
    splitT_k<<<dim3(D_/32, (H_*DH_)/32), dim3(32,8)>>>(wo, woh, wol, H_*DH_, D_);

    // QKV projections (tensor core, fp32 out)
    gemm_bf16<<<dim3((H_*DH_)/128,  BS_/128), 256, 8*TILE_BYTES>>>(xh, xl, wqh, wql, q, BS_, H_*DH_,  D_);
    gemm_bf16<<<dim3((HKV_*DH_)/128, BS_/128), 256, 8*TILE_BYTES>>>(xh, xl, wkh, wkl, k, BS_, HKV_*DH_, D_);
    gemm_bf16<<<dim3((HKV_*DH_)/128, BS_/128), 256, 8*TILE_BYTES>>>(xh, xl, wvh, wvl, v, BS_, HKV_*DH_, D_);

    // RoPE + scale + bf16 hi/lo split + head-major relayout
    {
        int total = B_ * S_ * (H_ + HKV_) * 64;
        ropesplit_qk<<<(total + 255)/256, 256>>>(q, k, pos, fqh, fql, fkh, fkl);
        int tv = B_ * S_ * HKV_ * DH_;
        split_v<<<(tv + 255)/256, 256>>>(v, fvh, fvl);
    }

    // tensor-core causal flash attention -> oh/ol (bf16 hi/lo)
    flash_tc<<<dim3(S_/64, H_, B_), 128, FLASH_SMEM>>>(fqh, fql, fkh, fkl,
                                                       fvh, fvl, oh, ol);

    // output projection
    gemm_bf16<<<dim3(D_/128, BS_/128), 256, 8*TILE_BYTES>>>(oh, ol, woh, wol, out, BS_, D_, D_);
}

// round 6
// speedup vs baseline: 3.1108x; 1.0240x over previous
#include <cuda_runtime.h>
#include <cuda_bf16.h>
#include <math.h>
#include <stdint.h>

#define B_    2
#define S_    2048
#define D_    2048
#define H_    16
#define HKV_  4
#define DH_   128
#define NREP_ (H_/HKV_)
#define BS_   (B_*S_)

// ---------------- scratch (static device allocations) ------------------
__device__ float g_q[BS_*H_*DH_];
__device__ float g_k[BS_*HKV_*DH_];
__device__ float g_v[BS_*HKV_*DH_];

__device__ __nv_bfloat16 g_xh[BS_*D_],  g_xl[BS_*D_];
__device__ __nv_bfloat16 g_oh[BS_*H_*DH_], g_ol[BS_*H_*DH_];
__device__ __nv_bfloat16 g_wqh[(H_*DH_)*D_],  g_wql[(H_*DH_)*D_];   // [N][K]
__device__ __nv_bfloat16 g_wkh[(HKV_*DH_)*D_], g_wkl[(HKV_*DH_)*D_];
__device__ __nv_bfloat16 g_wvh[(HKV_*DH_)*D_], g_wvl[(HKV_*DH_)*D_];
__device__ __nv_bfloat16 g_woh[D_*(H_*DH_)],  g_wol[D_*(H_*DH_)];

__device__ __nv_bfloat16 g_fqh[(size_t)B_*H_*S_*DH_],   g_fql[(size_t)B_*H_*S_*DH_];
__device__ __nv_bfloat16 g_fkh[(size_t)B_*HKV_*S_*DH_], g_fkl[(size_t)B_*HKV_*S_*DH_];
__device__ __nv_bfloat16 g_fvh[(size_t)B_*HKV_*S_*DH_], g_fvl[(size_t)B_*HKV_*S_*DH_];

// ---------------- common helpers ---------------------------------------
__device__ __forceinline__ void cp16(void* smem, const void* gmem) {
    uint32_t s = (uint32_t)__cvta_generic_to_shared(smem);
    asm volatile("cp.async.cg.shared.global [%0], [%1], 16;" :: "r"(s), "l"(gmem));
}
__device__ __forceinline__ void mma16816(float* c, const uint32_t* a, const uint32_t* b) {
    asm volatile("mma.sync.aligned.m16n8k16.row.col.f32.bf16.bf16.f32 "
        "{%0,%1,%2,%3}, {%4,%5,%6,%7}, {%8,%9}, {%0,%1,%2,%3};"
        : "+f"(c[0]), "+f"(c[1]), "+f"(c[2]), "+f"(c[3])
        : "r"(a[0]), "r"(a[1]), "r"(a[2]), "r"(a[3]), "r"(b[0]), "r"(b[1]));
}
__device__ __forceinline__ void ldmx4(uint32_t* r, uint32_t addr) {
    asm volatile("ldmatrix.sync.aligned.m8n8.x4.shared.b16 {%0,%1,%2,%3}, [%4];"
        : "=r"(r[0]), "=r"(r[1]), "=r"(r[2]), "=r"(r[3]) : "r"(addr));
}
__device__ __forceinline__ void ldmx4t(uint32_t* r, uint32_t addr) {
    asm volatile("ldmatrix.sync.aligned.m8n8.x4.trans.shared.b16 {%0,%1,%2,%3}, [%4];"
        : "=r"(r[0]), "=r"(r[1]), "=r"(r[2]), "=r"(r[3]) : "r"(addr));
}
__device__ __forceinline__ void pack_hl(float a, float b, uint32_t& hi, uint32_t& lo) {
    __nv_bfloat162 h2 = __floats2bfloat162_rn(a, b);
    hi = *(uint32_t*)&h2;
    __nv_bfloat162 l2 = __floats2bfloat162_rn(a - __bfloat162float(h2.x),
                                              b - __bfloat162float(h2.y));
    lo = *(uint32_t*)&l2;
}

// ---------------- fp32 -> bf16 hi/lo split (same layout) ---------------
__global__ __launch_bounds__(256) void split_k(const float* __restrict__ in,
                                               __nv_bfloat16* __restrict__ hi,
                                               __nv_bfloat16* __restrict__ lo,
                                               int n)
{
    int i = blockIdx.x * 256 + threadIdx.x;
    if (i < n) {
        float v = in[i];
        __nv_bfloat16 h = __float2bfloat16_rn(v);
        hi[i] = h;
        lo[i] = __float2bfloat16_rn(v - __bfloat162float(h));
    }
}

// ---------------- fp32 [K][N] -> bf16 hi/lo transposed [N][K] ----------
__global__ __launch_bounds__(256) void splitT_k(const float* __restrict__ w,
                                                __nv_bfloat16* __restrict__ th,
                                                __nv_bfloat16* __restrict__ tl,
                                                int K, int N)
{
    __shared__ float t[32][33];
    const int bx = blockIdx.x, by = blockIdx.y;
    const int tx = threadIdx.x, ty = threadIdx.y;   // 32 x 8
    #pragma unroll
    for (int j = 0; j < 4; j++)
        t[ty + j * 8][tx] = w[(size_t)(by * 32 + ty + j * 8) * N + bx * 32 + tx];
    __syncthreads();
    #pragma unroll
    for (int j = 0; j < 4; j++) {
        int n  = bx * 32 + ty + j * 8;
        int kc = by * 32 + tx;
        float v = t[tx][ty + j * 8];
        __nv_bfloat16 h = __float2bfloat16_rn(v);
        th[(size_t)n * K + kc] = h;
        tl[(size_t)n * K + kc] = __float2bfloat16_rn(v - __bfloat162float(h));
    }
}

// ---------------- bf16-split tensor-core GEMM (v2) ---------------------
// CTA 128x128, BK=32, 4 warps (2x2), warp tile 64x64, ldmatrix fragments.
#define LDB 40
#define TILE_HALVES (128*LDB)
#define TILE_BYTES  (TILE_HALVES*2)

__global__ __launch_bounds__(128) void gemm_bf16(const __nv_bfloat16* __restrict__ Ah,
                                                 const __nv_bfloat16* __restrict__ Al,
                                                 const __nv_bfloat16* __restrict__ Bh,
                                                 const __nv_bfloat16* __restrict__ Bl,
                                                 float* __restrict__ C,
                                                 int M, int N, int K)
{
    extern __shared__ char smem_raw[];
    const int tid  = threadIdx.x;
    const int lane = tid & 31, warp = tid >> 5;
    const int wm = warp >> 1, wn = warp & 1;
    const int aRow0 = blockIdx.y * 128;
    const int bRow0 = blockIdx.x * 128;

    float acc[4][8][4];
    #pragma unroll
    for (int mi = 0; mi < 4; mi++)
        #pragma unroll
        for (int ni = 0; ni < 8; ni++)
            #pragma unroll
            for (int e = 0; e < 4; e++) acc[mi][ni][e] = 0.f;

    const int nchunk = K / 32;

    // ldmatrix per-lane address offsets (in halves, relative to tile base)
    // A (16x16 tile): lanes 0-15 rows 0-15 @k0, lanes 16-31 rows 0-15 @k8
    const int aoff = (lane & 15) * LDB + ((lane >> 4) << 3);
    // B (two 8-row n tiles x k16): l0-7 n0-7@k0, l8-15 n0-7@k8, l16-23 n8-15@k0, l24-31 n8-15@k8
    const int boff = ((lane & 7) + ((lane >> 4) << 3)) * LDB + (((lane >> 3) & 1) << 3);

    {
        char* stg = smem_raw;
        __nv_bfloat16* AsH = (__nv_bfloat16*)stg;
        __nv_bfloat16* AsL = AsH + TILE_HALVES;
        __nv_bfloat16* BtH = AsL + TILE_HALVES;
        __nv_bfloat16* BtL = BtH + TILE_HALVES;
        #pragma unroll
        for (int s = tid; s < 512; s += 128) {
            int row = s >> 2, kg = (s & 3) * 8;
            size_t ga = (size_t)(aRow0 + row) * K + kg;
            size_t gb = (size_t)(bRow0 + row) * K + kg;
            cp16(&AsH[row * LDB + kg], Ah + ga);
            cp16(&AsL[row * LDB + kg], Al + ga);
            cp16(&BtH[row * LDB + kg], Bh + gb);
            cp16(&BtL[row * LDB + kg], Bl + gb);
        }
        asm volatile("cp.async.commit_group;" ::: "memory");
    }

    for (int c = 0; c < nchunk; c++) {
        char* cur = smem_raw + (c & 1) * 4 * TILE_BYTES;
        char* nxt = smem_raw + ((c + 1) & 1) * 4 * TILE_BYTES;

        if (c + 1 < nchunk) {
            int k0 = (c + 1) * 32;
            __nv_bfloat16* AsH = (__nv_bfloat16*)nxt;
            __nv_bfloat16* AsL = AsH + TILE_HALVES;
            __nv_bfloat16* BtH = AsL + TILE_HALVES;
            __nv_bfloat16* BtL = BtH + TILE_HALVES;
            #pragma unroll
            for (int s = tid; s < 512; s += 128) {
                int row = s >> 2, kg = (s & 3) * 8;
                size_t ga = (size_t)(aRow0 + row) * K + k0 + kg;
                size_t gb = (size_t)(bRow0 + row) * K + k0 + kg;
                cp16(&AsH[row * LDB + kg], Ah + ga);
                cp16(&AsL[row * LDB + kg], Al + ga);
                cp16(&BtH[row * LDB + kg], Bh + gb);
                cp16(&BtL[row * LDB + kg], Bl + gb);
            }
            asm volatile("cp.async.commit_group;" ::: "memory");
            asm volatile("cp.async.wait_group 1;" ::: "memory");
        } else {
            asm volatile("cp.async.wait_group 0;" ::: "memory");
        }
        __syncthreads();

        const __nv_bfloat16* AsH = (const __nv_bfloat16*)cur;
        const __nv_bfloat16* AsL = AsH + TILE_HALVES;
        const __nv_bfloat16* BtH = AsL + TILE_HALVES;
        const __nv_bfloat16* BtL = BtH + TILE_HALVES;

        #pragma unroll
        for (int ks = 0; ks < 32; ks += 16) {
            uint32_t ah[4][4], al[4][4], bh[8][2], bl[8][2];
            #pragma unroll
            for (int mi = 0; mi < 4; mi++) {
                int base = (wm * 64 + mi * 16) * LDB + ks;
                ldmx4(ah[mi], (uint32_t)__cvta_generic_to_shared(AsH + base + aoff));
                ldmx4(al[mi], (uint32_t)__cvta_generic_to_shared(AsL + base + aoff));
            }
            #pragma unroll
            for (int ni = 0; ni < 8; ni += 2) {
                int base = (wn * 64 + ni * 8) * LDB + ks;
                uint32_t th_[4], tl_[4];
                ldmx4(th_, (uint32_t)__cvta_generic_to_shared(BtH + base + boff));
                ldmx4(tl_, (uint32_t)__cvta_generic_to_shared(BtL + base + boff));
                bh[ni][0] = th_[0]; bh[ni][1] = th_[1];
                bh[ni+1][0] = th_[2]; bh[ni+1][1] = th_[3];
                bl[ni][0] = tl_[0]; bl[ni][1] = tl_[1];
                bl[ni+1][0] = tl_[2]; bl[ni+1][1] = tl_[3];
            }
            #pragma unroll
            for (int mi = 0; mi < 4; mi++)
                #pragma unroll
                for (int ni = 0; ni < 8; ni++) {
                    mma16816(acc[mi][ni], ah[mi], bh[ni]);
                    mma16816(acc[mi][ni], ah[mi], bl[ni]);
                    mma16816(acc[mi][ni], al[mi], bh[ni]);
                }
        }
        __syncthreads();
    }

    #pragma unroll
    for (int mi = 0; mi < 4; mi++)
        #pragma unroll
        for (int ni = 0; ni < 8; ni++) {
            int row = aRow0 + wm * 64 + mi * 16 + (lane >> 2);
            int col = bRow0 + wn * 64 + ni * 8 + (lane & 3) * 2;
            *(float2*)&C[(size_t)row * N + col] =
                make_float2(acc[mi][ni][0], acc[mi][ni][1]);
            *(float2*)&C[(size_t)(row + 8) * N + col] =
                make_float2(acc[mi][ni][2], acc[mi][ni][3]);
        }
}

// ---------- RoPE + scale + split + relayout for Q and K ----------------
__global__ __launch_bounds__(256) void ropesplit_qk(
    const float* __restrict__ q, const float* __restrict__ k,
    const int* __restrict__ pos,
    __nv_bfloat16* __restrict__ qh, __nv_bfloat16* __restrict__ ql,
    __nv_bfloat16* __restrict__ kh, __nv_bfloat16* __restrict__ kl)
{
    int idx = blockIdx.x * 256 + threadIdx.x;
    const int total = B_ * S_ * (H_ + HKV_) * 64;
    if (idx >= total) return;
    int i = idx & 63; idx >>= 6;
    int head = idx % (H_ + HKV_); idx /= (H_ + HKV_);
    int s = idx % S_;
    int b = idx / S_;
    float p = (float)pos[b * S_ + s];
    float invf = powf(10000.0f, -(float)i / 64.0f);
    float sn, cs;
    sincosf(p * invf, &sn, &cs);
    const float scale = 0.08838834764831845f;

    if (head < H_) {
        const float* src = q + ((size_t)(b * S_ + s) * H_ + head) * DH_;
        float x1 = src[i], x2 = src[i + 64];
        float y1 = (x1 * cs - x2 * sn) * scale;
        float y2 = (x2 * cs + x1 * sn) * scale;
        size_t dst = ((size_t)(b * H_ + head) * S_ + s) * DH_;
        __nv_bfloat16 h1 = __float2bfloat16_rn(y1);
        __nv_bfloat16 h2 = __float2bfloat16_rn(y2);
        qh[dst + i]      = h1;
        ql[dst + i]      = __float2bfloat16_rn(y1 - __bfloat162float(h1));
        qh[dst + i + 64] = h2;
        ql[dst + i + 64] = __float2bfloat16_rn(y2 - __bfloat162float(h2));
    } else {
        int hk = head - H_;
        const float* src = k + ((size_t)(b * S_ + s) * HKV_ + hk) * DH_;
        float x1 = src[i], x2 = src[i + 64];
        float y1 = x1 * cs - x2 * sn;
        float y2 = x2 * cs + x1 * sn;
        size_t dst = ((size_t)(b * HKV_ + hk) * S_ + s) * DH_;
        __nv_bfloat16 h1 = __float2bfloat16_rn(y1);
        __nv_bfloat16 h2 = __float2bfloat16_rn(y2);
        kh[dst + i]      = h1;
        kl[dst + i]      = __float2bfloat16_rn(y1 - __bfloat162float(h1));
        kh[dst + i + 64] = h2;
        kl[dst + i + 64] = __float2bfloat16_rn(y2 - __bfloat162float(h2));
    }
}

// ---------- V split + relayout -----------------------------------------
__global__ __launch_bounds__(256) void split_v(const float* __restrict__ v,
                                               __nv_bfloat16* __restrict__ vh,
                                               __nv_bfloat16* __restrict__ vl)
{
    int idx = blockIdx.x * 256 + threadIdx.x;
    const int total = B_ * S_ * HKV_ * DH_;
    if (idx >= total) return;
    int d = idx & 127; int t = idx >> 7;
    int hk = t % HKV_; t /= HKV_;
    int s = t % S_; int b = t / S_;
    float x = v[((size_t)(b * S_ + s) * HKV_ + hk) * DH_ + d];
    size_t dst = ((size_t)(b * HKV_ + hk) * S_ + s) * DH_ + d;
    __nv_bfloat16 h = __float2bfloat16_rn(x);
    vh[dst] = h;
    vl[dst] = __float2bfloat16_rn(x - __bfloat162float(h));
}

// ---------------- tensor-core flash attention --------------------------
#define FP   136
#define FLASH_SMEM (4 * 64 * FP * 2)

__global__ __launch_bounds__(128) void flash_tc(
    const __nv_bfloat16* __restrict__ qh, const __nv_bfloat16* __restrict__ ql,
    const __nv_bfloat16* __restrict__ kh, const __nv_bfloat16* __restrict__ kl,
    const __nv_bfloat16* __restrict__ vh, const __nv_bfloat16* __restrict__ vl,
    __nv_bfloat16* __restrict__ oh, __nv_bfloat16* __restrict__ ol)
{
    extern __shared__ __nv_bfloat16 smh[];
    __nv_bfloat16* Kh_s = smh;
    __nv_bfloat16* Kl_s = Kh_s + 64 * FP;
    __nv_bfloat16* Vh_s = Kl_s + 64 * FP;
    __nv_bfloat16* Vl_s = Vh_s + 64 * FP;

    const int m0 = blockIdx.x * 64;
    const int h  = blockIdx.y, b = blockIdx.z;
    const int hkv = h / NREP_;
    const int tid = threadIdx.x, lane = tid & 31, warp = tid >> 5;

    const size_t qbase = ((size_t)(b * H_ + h) * S_ + m0) * DH_;
    const size_t kvb   = ((size_t)(b * HKV_ + hkv) * S_) * DH_;

    for (int i = tid; i < 1024; i += 128) {
        int r = i >> 4, ck = (i & 15) << 3;
        cp16(&Vh_s[r * FP + ck], qh + qbase + r * DH_ + ck);
        cp16(&Vl_s[r * FP + ck], ql + qbase + r * DH_ + ck);
    }
    asm volatile("cp.async.commit_group;\ncp.async.wait_group 0;" ::: "memory");
    __syncthreads();

    uint32_t qfh[8][4], qfl[8][4];
    {
        int r0 = warp * 16 + (lane >> 2);
        int kq = (lane & 3) * 2;
        #pragma unroll
        for (int c = 0; c < 8; c++) {
            int o0 = r0 * FP + c * 16 + kq;
            int o1 = (r0 + 8) * FP + c * 16 + kq;
            qfh[c][0] = *(uint32_t*)&Vh_s[o0];
            qfh[c][1] = *(uint32_t*)&Vh_s[o1];
            qfh[c][2] = *(uint32_t*)&Vh_s[o0 + 8];
            qfh[c][3] = *(uint32_t*)&Vh_s[o1 + 8];
            qfl[c][0] = *(uint32_t*)&Vl_s[o0];
            qfl[c][1] = *(uint32_t*)&Vl_s[o1];
            qfl[c][2] = *(uint32_t*)&Vl_s[o0 + 8];
            qfl[c][3] = *(uint32_t*)&Vl_s[o1 + 8];
        }
    }
    __syncthreads();

    float acc[16][4];
    #pragma unroll
    for (int nj = 0; nj < 16; nj++)
        #pragma unroll
        for (int e = 0; e < 4; e++) acc[nj][e] = 0.f;
    float m_i[2] = {-1e30f, -1e30f}, l_i[2] = {0.f, 0.f};

    for (int n0 = 0; n0 <= m0; n0 += 64) {
        for (int i = tid; i < 1024; i += 128) {
            int r = i >> 4, ck = (i & 15) << 3;
            size_t g = kvb + (size_t)(n0 + r) * DH_ + ck;
            cp16(&Kh_s[r * FP + ck], kh + g);
            cp16(&Kl_s[r * FP + ck], kl + g);
            cp16(&Vh_s[r * FP + ck], vh + g);
            cp16(&Vl_s[r * FP + ck], vl + g);
        }
        asm volatile("cp.async.commit_group;\ncp.async.wait_group 0;" ::: "memory");
        __syncthreads();

        float sf[8][4];
        #pragma unroll
        for (int j = 0; j < 8; j++)
            #pragma unroll
            for (int e = 0; e < 4; e++) sf[j][e] = 0.f;

        #pragma unroll
        for (int c = 0; c < 8; c++) {
            #pragma unroll
            for (int j = 0; j < 8; j++) {
                int base = (j * 8 + (lane >> 2)) * FP + c * 16 + (lane & 3) * 2;
                uint32_t bhf[2] = { *(uint32_t*)&Kh_s[base], *(uint32_t*)&Kh_s[base + 8] };
                uint32_t blf[2] = { *(uint32_t*)&Kl_s[base], *(uint32_t*)&Kl_s[base + 8] };
                mma16816(sf[j], qfh[c], bhf);
                mma16816(sf[j], qfh[c], blf);
                mma16816(sf[j], qfl[c], bhf);
            }
        }

        if (n0 == m0) {
            int r0 = m0 + warp * 16 + (lane >> 2);
            #pragma unroll
            for (int j = 0; j < 8; j++)
                #pragma unroll
                for (int e = 0; e < 4; e++) {
                    int col = n0 + j * 8 + (lane & 3) * 2 + (e & 1);
                    int row = r0 + ((e >> 1) << 3);
                    if (col > row) sf[j][e] = -1e30f;
                }
        }

        #pragma unroll
        for (int rh = 0; rh < 2; rh++) {
            float mx = -1e30f;
            #pragma unroll
            for (int j = 0; j < 8; j++)
                mx = fmaxf(mx, fmaxf(sf[j][2 * rh], sf[j][2 * rh + 1]));
            mx = fmaxf(mx, __shfl_xor_sync(0xffffffffu, mx, 1));
            mx = fmaxf(mx, __shfl_xor_sync(0xffffffffu, mx, 2));
            float mn = fmaxf(m_i[rh], mx);
            float alpha = __expf(m_i[rh] - mn);
            float rs = 0.f;
            #pragma unroll
            for (int j = 0; j < 8; j++) {
                sf[j][2 * rh]     = __expf(sf[j][2 * rh] - mn);
                sf[j][2 * rh + 1] = __expf(sf[j][2 * rh + 1] - mn);
                rs += sf[j][2 * rh] + sf[j][2 * rh + 1];
            }
            rs += __shfl_xor_sync(0xffffffffu, rs, 1);
            rs += __shfl_xor_sync(0xffffffffu, rs, 2);
            l_i[rh] = l_i[rh] * alpha + rs;
            m_i[rh] = mn;
            #pragma unroll
            for (int nj = 0; nj < 16; nj++) {
                acc[nj][2 * rh]     *= alpha;
                acc[nj][2 * rh + 1] *= alpha;
            }
        }

        uint32_t ph[4][4], pl[4][4];
        #pragma unroll
        for (int kc = 0; kc < 4; kc++) {
            pack_hl(sf[2*kc][0],   sf[2*kc][1],   ph[kc][0], pl[kc][0]);
            pack_hl(sf[2*kc][2],   sf[2*kc][3],   ph[kc][1], pl[kc][1]);
            pack_hl(sf[2*kc+1][0], sf[2*kc+1][1], ph[kc][2], pl[kc][2]);
            pack_hl(sf[2*kc+1][2], sf[2*kc+1][3], ph[kc][3], pl[kc][3]);
        }

        int g  = lane >> 3, rr = lane & 7;
        #pragma unroll
        for (int kc = 0; kc < 4; kc++) {
            int vrow = kc * 16 + rr + ((g & 1) << 3);
            #pragma unroll
            for (int nj = 0; nj < 16; nj += 2) {
                int vcol = (nj + (g >> 1)) * 8;
                uint32_t ah = (uint32_t)__cvta_generic_to_shared(&Vh_s[vrow * FP + vcol]);
                uint32_t al = (uint32_t)__cvta_generic_to_shared(&Vl_s[vrow * FP + vcol]);
                uint32_t vbh[4], vbl[4];
                ldmx4t(vbh, ah);
                ldmx4t(vbl, al);
                mma16816(acc[nj],     ph[kc], vbh);
                mma16816(acc[nj],     ph[kc], vbl);
                mma16816(acc[nj],     pl[kc], vbh);
                mma16816(acc[nj + 1], ph[kc], vbh + 2);
                mma16816(acc[nj + 1], ph[kc], vbl + 2);
                mma16816(acc[nj + 1], pl[kc], vbh + 2);
            }
        }
        __syncthreads();
    }

    float inv0 = 1.0f / l_i[0], inv1 = 1.0f / l_i[1];
    int r0 = m0 + warp * 16 + (lane >> 2);
    size_t rowA = ((size_t)(b * S_ + r0)) * (H_ * DH_) + h * DH_;
    #pragma unroll
    for (int nj = 0; nj < 16; nj++) {
        int cc = nj * 8 + (lane & 3) * 2;
        float v0 = acc[nj][0] * inv0, v1 = acc[nj][1] * inv0;
        float v2 = acc[nj][2] * inv1, v3 = acc[nj][3] * inv1;
        __nv_bfloat162 h01 = __floats2bfloat162_rn(v0, v1);
        __nv_bfloat162 l01 = __floats2bfloat162_rn(v0 - __bfloat162float(h01.x),
                                                   v1 - __bfloat162float(h01.y));
        *(__nv_bfloat162*)&oh[rowA + cc] = h01;
        *(__nv_bfloat162*)&ol[rowA + cc] = l01;
        __nv_bfloat162 h23 = __floats2bfloat162_rn(v2, v3);
        __nv_bfloat162 l23 = __floats2bfloat162_rn(v2 - __bfloat162float(h23.x),
                                                   v3 - __bfloat162float(h23.y));
        *(__nv_bfloat162*)&oh[rowA + (size_t)8 * (H_ * DH_) + cc] = h23;
        *(__nv_bfloat162*)&ol[rowA + (size_t)8 * (H_ * DH_) + cc] = l23;
    }
}

extern "C" void kernel_launch(void* const* d_in, const int* in_sizes, int n_in,
                              void* d_out, int out_size)
{
    const float* x   = (const float*)d_in[0];
    const int*   pos = (const int*)  d_in[1];
    const float* wq  = (const float*)d_in[2];
    const float* wk  = (const float*)d_in[3];
    const float* wv  = (const float*)d_in[4];
    const float* wo  = (const float*)d_in[5];
    float* out = (float*)d_out;

    float *q, *k, *v;
    cudaGetSymbolAddress((void**)&q, g_q);
    cudaGetSymbolAddress((void**)&k, g_k);
    cudaGetSymbolAddress((void**)&v, g_v);

    __nv_bfloat16 *xh, *xl, *oh, *ol, *wqh, *wql, *wkh, *wkl, *wvh, *wvl, *woh, *wol;
    cudaGetSymbolAddress((void**)&xh,  g_xh);  cudaGetSymbolAddress((void**)&xl,  g_xl);
    cudaGetSymbolAddress((void**)&oh,  g_oh);  cudaGetSymbolAddress((void**)&ol,  g_ol);
    cudaGetSymbolAddress((void**)&wqh, g_wqh); cudaGetSymbolAddress((void**)&wql, g_wql);
    cudaGetSymbolAddress((void**)&wkh, g_wkh); cudaGetSymbolAddress((void**)&wkl, g_wkl);
    cudaGetSymbolAddress((void**)&wvh, g_wvh); cudaGetSymbolAddress((void**)&wvl, g_wvl);
    cudaGetSymbolAddress((void**)&woh, g_woh); cudaGetSymbolAddress((void**)&wol, g_wol);

    __nv_bfloat16 *fqh, *fql, *fkh, *fkl, *fvh, *fvl;
    cudaGetSymbolAddress((void**)&fqh, g_fqh); cudaGetSymbolAddress((void**)&fql, g_fql);
    cudaGetSymbolAddress((void**)&fkh, g_fkh); cudaGetSymbolAddress((void**)&fkl, g_fkl);
    cudaGetSymbolAddress((void**)&fvh, g_fvh); cudaGetSymbolAddress((void**)&fvl, g_fvl);

    cudaFuncSetAttribute(gemm_bf16, cudaFuncAttributeMaxDynamicSharedMemorySize,
                         8 * TILE_BYTES);
    cudaFuncSetAttribute(flash_tc, cudaFuncAttributeMaxDynamicSharedMemorySize,
                         FLASH_SMEM);

    split_k<<<(BS_*D_ + 255)/256, 256>>>(x, xh, xl, BS_*D_);
    splitT_k<<<dim3((H_*DH_)/32,  D_/32), dim3(32,8)>>>(wq, wqh, wql, D_, H_*DH_);
    splitT_k<<<dim3((HKV_*DH_)/32, D_/32), dim3(32,8)>>>(wk, wkh, wkl, D_, HKV_*DH_);
    splitT_k<<<dim3((HKV_*DH_)/32, D_/32), dim3(32,8)>>>(wv, wvh, wvl, D_, HKV_*DH_);
    splitT_k<<<dim3(D_/32, (H_*DH_)/32), dim3(32,8)>>>(wo, woh, wol, H_*DH_, D_);

    gemm_bf16<<<dim3((H_*DH_)/128,  BS_/128), 128, 8*TILE_BYTES>>>(xh, xl, wqh, wql, q, BS_, H_*DH_,  D_);
    gemm_bf16<<<dim3((HKV_*DH_)/128, BS_/128), 128, 8*TILE_BYTES>>>(xh, xl, wkh, wkl, k, BS_, HKV_*DH_, D_);
    gemm_bf16<<<dim3((HKV_*DH_)/128, BS_/128), 128, 8*TILE_BYTES>>>(xh, xl, wvh, wvl, v, BS_, HKV_*DH_, D_);

    {
        int total = B_ * S_ * (H_ + HKV_) * 64;
        ropesplit_qk<<<(total + 255)/256, 256>>>(q, k, pos, fqh, fql, fkh, fkl);
        int tv = B_ * S_ * HKV_ * DH_;
        split_v<<<(tv + 255)/256, 256>>>(v, fvh, fvl);
    }

    flash_tc<<<dim3(S_/64, H_, B_), 128, FLASH_SMEM>>>(fqh, fql, fkh, fkl,
                                                       fvh, fvl, oh, ol);

    gemm_bf16<<<dim3(D_/128, BS_/128), 128, 8*TILE_BYTES>>>(oh, ol, woh, wol, out, BS_, D_, D_);
}